// round 10
// baseline (speedup 1.0000x reference)
#include <cuda_runtime.h>
#include <cstdint>

// ---------------------------------------------------------------------------
// DRQN fused pipeline (sm_103 base ISA: legacy mma.sync tf32 + cp.async).
// R10: 2 CTAs/SM (warp tile 64x32, BN=128, regs<=128) to fix the occ=12.4%/
// tensor=45.6% latency bind seen in R9. Operands pre-rounded to tf32 once.
//
// NOTE: __device__ globals are ONLY referenced from device code (GB300 ATS
// silently reads the host shadow if passed as host-side kernel args).
//
//   hvec = W_hh@h + b_ih + b_hh
//   x    = relu(g_in @ W1^T + b1)        GEMM1 BM128 BN128
//   gates= x @ Wih^T (gate-interleaved) -> LSTM cell   GEMM2 BM128 BN128
//   q    = h @ W2^T + b2                 GEMM3 BM128 BN32
// Output: [ q (B*32) | h_new[B-1] (512) | c_new[B-1] (512) ]
// ---------------------------------------------------------------------------

#define B_ROWS 32768
#define OBS    512
#define ACT    32
#define KIN    544
#define EMB    512
#define HID    512
#define NQ     32

__device__ float g_in[(size_t)B_ROWS * KIN];
__device__ float g_x [(size_t)B_ROWS * EMB];
__device__ float g_h [(size_t)B_ROWS * HID];
__device__ float g_w1 [EMB * KIN];
__device__ float g_wih[4 * HID * EMB];
__device__ float g_w2 [NQ * HID];
__device__ float g_hvec[4 * HID];

// ------------------------------ helpers -----------------------------------
__device__ __forceinline__ uint32_t smem_u32(const void* p) {
    uint32_t a;
    asm("{ .reg .u64 t; cvta.to.shared.u64 t, %1; cvt.u32.u64 %0, t; }"
        : "=r"(a) : "l"(p));
    return a;
}
__device__ __forceinline__ uint32_t tf32r(float f) {
    uint32_t u; asm("cvt.rna.tf32.f32 %0, %1;" : "=r"(u) : "f"(f)); return u;
}
__device__ __forceinline__ float tf32f(float f) { return __uint_as_float(tf32r(f)); }
__device__ __forceinline__ float4 r4(float4 v) {
    v.x = tf32f(v.x); v.y = tf32f(v.y); v.z = tf32f(v.z); v.w = tf32f(v.w);
    return v;
}
__device__ __forceinline__ void ldsm4(uint32_t* r, uint32_t addr) {
    asm volatile("ldmatrix.sync.aligned.m8n8.x4.shared.b16 {%0,%1,%2,%3}, [%4];"
                 : "=r"(r[0]), "=r"(r[1]), "=r"(r[2]), "=r"(r[3]) : "r"(addr));
}
__device__ __forceinline__ void mma_tf(float* c, const uint32_t* a,
                                       uint32_t b0, uint32_t b1) {
    asm volatile(
        "mma.sync.aligned.m16n8k8.row.col.f32.tf32.tf32.f32 "
        "{%0,%1,%2,%3}, {%4,%5,%6,%7}, {%8,%9}, {%0,%1,%2,%3};"
        : "+f"(c[0]), "+f"(c[1]), "+f"(c[2]), "+f"(c[3])
        : "r"(a[0]), "r"(a[1]), "r"(a[2]), "r"(a[3]), "r"(b0), "r"(b1));
}
#define CP16(dst, src) asm volatile("cp.async.cg.shared.global [%0], [%1], 16;" :: "r"(dst), "l"(src) : "memory")
#define CP_COMMIT()    asm volatile("cp.async.commit_group;" ::: "memory")
#define CP_WAIT2()     asm volatile("cp.async.wait_group 2;" ::: "memory")

__device__ __forceinline__ float sigmoidf_(float x) {
    return __fdividef(1.f, 1.f + __expf(-x));
}
__device__ __forceinline__ float tanhf_(float x) {
    return __fdividef(2.f, 1.f + __expf(-2.f * x)) - 1.f;
}

// ---------------------------------------------------------------------------
// Pre-pass: pack [obs|act] rounded into g_in; round weight copies.
// ---------------------------------------------------------------------------
__global__ void __launch_bounds__(256) pack_in_kernel(
    const float* __restrict__ obs, const float* __restrict__ act)
{
    int id = blockIdx.x * 256 + threadIdx.x;           // over B_ROWS*136 float4
    if (id >= B_ROWS * 136) return;
    int b = id / 136, c4 = (id - b * 136) * 4;
    float4 v = (c4 < OBS) ? *(const float4*)(obs + (size_t)b * OBS + c4)
                          : *(const float4*)(act + (size_t)b * ACT + (c4 - OBS));
    *(float4*)(g_in + (size_t)b * KIN + c4) = r4(v);
}
__global__ void __launch_bounds__(256) conv_w_kernel(
    const float* __restrict__ W1, const float* __restrict__ Wih,
    const float* __restrict__ W2)
{
    int id = blockIdx.x * 256 + threadIdx.x;           // float4 index
    const int N1 = EMB * KIN / 4, N2 = N1 + 4 * HID * EMB / 4;
    const int N3 = N2 + NQ * HID / 4;
    if (id < N1)      *(float4*)(g_w1  + 4 * id)        = r4(*(const float4*)(W1  + 4 * id));
    else if (id < N2) *(float4*)(g_wih + 4 * (id - N1)) = r4(*(const float4*)(Wih + 4 * (size_t)(id - N1)));
    else if (id < N3) *(float4*)(g_w2  + 4 * (id - N2)) = r4(*(const float4*)(W2  + 4 * (id - N2)));
}

// ---------------------------------------------------------------------------
// K0: hvec[n] = dot(W_hh[n,:], h) + b_ih[n] + b_hh[n]   (exact fp32)
// ---------------------------------------------------------------------------
__global__ void __launch_bounds__(256) hvec_kernel(
    const float* __restrict__ Whh, const float* __restrict__ h,
    const float* __restrict__ bih, const float* __restrict__ bhh)
{
    int w    = (blockIdx.x * blockDim.x + threadIdx.x) >> 5;
    int lane = threadIdx.x & 31;
    if (w >= 4 * HID) return;
    const float* row = Whh + (size_t)w * HID;
    float s = 0.f;
    #pragma unroll
    for (int k = 0; k < HID; k += 32) s += row[k + lane] * h[k + lane];
    #pragma unroll
    for (int o = 16; o > 0; o >>= 1) s += __shfl_xor_sync(0xffffffffu, s, o);
    if (lane == 0) g_hvec[w] = s + bih[w] + bhh[w];
}

// ---------------------------------------------------------------------------
// GEMM: BM=128, BN=128, BK=16, 256 thr (8 warps, warp tile 64x32), 4 stages,
// 2 CTAs/SM. MODE 0: relu GEMM1, grid (4, 256). MODE 1: gate-interleaved +
// LSTM cell, grid (16, 256), 32 hid/CTA.
// smem: [0,2048) aux | 4 stages x (A 8K | B 8K); MODE1 epilogue reuses tiles.
// ---------------------------------------------------------------------------
#define NS 4
#define STG 16384
#define GSMEM (2048 + NS * STG)      // 67584

template <int MODE>
__global__ void __launch_bounds__(256, 2) mma_gemm_kernel(
    const float* __restrict__ b1, const float* __restrict__ cell,
    float* __restrict__ out)
{
    constexpr int KA = (MODE == 0) ? KIN : EMB;
    constexpr int KT = KA / 16;
    // Device-side binding of scratch globals (NEVER pass from host: ATS trap).
    const float* gA = (MODE == 0) ? g_in : g_x;
    const float* gB = (MODE == 0) ? g_w1 : g_wih;

    extern __shared__ char smem[];
    float* s_aux = (float*)smem;
    char*  tiles = smem + 2048;
    float* s_epi = (float*)tiles;
    const uint32_t tiles_u = smem_u32(tiles);

    const int tid = threadIdx.x, lane = tid & 31, wid = tid >> 5;
    const int m0w = 64 * (wid & 1), n0w = 32 * (wid >> 1);
    const int rowBase = blockIdx.y * 128;
    const int colBase = blockIdx.x * 128;   // MODE 0
    const int hb      = blockIdx.x * 32;    // MODE 1

    if (MODE == 0) {
        if (tid < 128) s_aux[tid] = b1[colBase + tid];
    } else {
        if (tid < 32)  s_aux[tid] = cell[hb + tid];
        if (tid < 128) s_aux[32 + tid] = g_hvec[((tid >> 5) << 9) + hb + (tid & 31)];
    }

    // ---- cp.async pointers / smem offsets (2 A-chunks + 2 B-chunks/thread) --
    const char* aptr[2]; uint32_t aoff[2];
    const char* bptr[2]; uint32_t boff[2];
    #pragma unroll
    for (int j = 0; j < 2; j++) {
        int m = (tid + 256 * j) >> 2, c = tid & 3;
        aptr[j] = (const char*)(gA + (size_t)(rowBase + m) * KA + 4 * c);
        aoff[j] = m * 64 + ((c ^ (m & 3)) << 4);
        if (MODE == 0) {
            bptr[j] = (const char*)(gB + (size_t)(colBase + m) * KA + 4 * c);
        } else {
            int wr = ((m & 3) << 9) + hb + (m >> 2);    // 512*gate + hid
            bptr[j] = (const char*)(gB + (size_t)wr * EMB + 4 * c);
        }
        boff[j] = 8192 + aoff[j];
    }

    // ldmatrix lane constants
    const int a_m  = m0w + (lane & 15);
    const int a_cb = lane >> 4, a_sw = a_m & 3;
    const int b_n  = n0w + (lane & 7) + ((lane & 16) >> 1);
    const int b_cb = (lane >> 3) & 1, b_sw = b_n & 3;

    float acc[4][4][4];
    #pragma unroll
    for (int i = 0; i < 4; i++)
        #pragma unroll
        for (int j = 0; j < 4; j++)
            #pragma unroll
            for (int k = 0; k < 4; k++) acc[i][j][k] = 0.f;

    auto issue = [&](int t) {
        uint32_t base = tiles_u + (t & (NS - 1)) * STG;
        size_t ko = (size_t)t * 64;
        #pragma unroll
        for (int j = 0; j < 2; j++) CP16(base + aoff[j], aptr[j] + ko);
        #pragma unroll
        for (int j = 0; j < 2; j++) CP16(base + boff[j], bptr[j] + ko);
        CP_COMMIT();
    };
    auto compute = [&](int s) {
        const uint32_t Ab = tiles_u + s * STG, Bb = Ab + 8192;
        #pragma unroll
        for (int ks = 0; ks < 2; ks++) {
            uint32_t af[4][4], bf[2][4];
            #pragma unroll
            for (int mi = 0; mi < 4; mi++)
                ldsm4(af[mi], Ab + (a_m + 16 * mi) * 64 + (((2 * ks + a_cb) ^ a_sw) << 4));
            #pragma unroll
            for (int p = 0; p < 2; p++)
                ldsm4(bf[p], Bb + (b_n + 16 * p) * 64 + (((2 * ks + b_cb) ^ b_sw) << 4));
            #pragma unroll
            for (int mi = 0; mi < 4; mi++)
                #pragma unroll
                for (int ni = 0; ni < 4; ni++)
                    mma_tf(acc[mi][ni], af[mi],
                           bf[ni >> 1][(ni & 1) * 2], bf[ni >> 1][(ni & 1) * 2 + 1]);
        }
    };

    issue(0); issue(1); issue(2);
    for (int t = 0; t < KT; t++) {
        CP_WAIT2();
        __syncthreads();
        compute(t & (NS - 1));
        if (t + 3 < KT) issue(t + 3); else CP_COMMIT();   // keep group count
    }

    // ---------------- epilogue ----------------
    if (MODE == 0) {
        #pragma unroll
        for (int mi = 0; mi < 4; mi++) {
            int r = rowBase + m0w + 16 * mi + (lane >> 2);
            #pragma unroll
            for (int ni = 0; ni < 4; ni++) {
                int cl = n0w + 8 * ni + 2 * (lane & 3);
                float* d0 = g_x + (size_t)r * EMB + colBase + cl;
                *(float2*)d0 = make_float2(
                    tf32f(fmaxf(acc[mi][ni][0] + s_aux[cl], 0.f)),
                    tf32f(fmaxf(acc[mi][ni][1] + s_aux[cl + 1], 0.f)));
                *(float2*)(d0 + 8 * EMB) = make_float2(
                    tf32f(fmaxf(acc[mi][ni][2] + s_aux[cl], 0.f)),
                    tf32f(fmaxf(acc[mi][ni][3] + s_aux[cl + 1], 0.f)));
            }
        }
    } else {
        __syncthreads();                        // tiles -> s_epi reuse
        #pragma unroll
        for (int mi = 0; mi < 4; mi++) {
            #pragma unroll
            for (int ni = 0; ni < 4; ni++) {
                float c0 = acc[mi][ni][0], c1 = acc[mi][ni][1];
                float c2 = acc[mi][ni][2], c3 = acc[mi][ni][3];
                float e0 = __shfl_xor_sync(0xffffffffu, c0, 1);
                float e1 = __shfl_xor_sync(0xffffffffu, c1, 1);
                float e2 = __shfl_xor_sync(0xffffffffu, c2, 1);
                float e3 = __shfl_xor_sync(0xffffffffu, c3, 1);
                bool ev = !(lane & 1);
                int rl = m0w + 16 * mi + (lane >> 2) + (ev ? 0 : 8);
                float gi = ev ? c0 : e2;
                float gf = ev ? c1 : e3;
                float gg = ev ? e0 : c2;
                float go = ev ? e1 : c3;
                int hl = (n0w >> 2) + 2 * ni + ((lane & 3) >> 1);
                float iv = sigmoidf_(gi + s_aux[32 + hl]);
                float fv = sigmoidf_(gf + s_aux[64 + hl]);
                float gv = tanhf_   (gg + s_aux[96 + hl]);
                float ov = sigmoidf_(go + s_aux[128 + hl]);
                float cn = fv * s_aux[hl] + iv * gv;
                float hn = ov * tanhf_(cn);
                s_epi[rl * 36 + hl] = tf32f(hn);
                if (rowBase + rl == B_ROWS - 1) {
                    out[(size_t)B_ROWS * NQ + hb + hl]       = hn;
                    out[(size_t)B_ROWS * NQ + HID + hb + hl] = cn;
                }
            }
        }
        __syncthreads();
        #pragma unroll
        for (int i = 0; i < 4; i++) {
            int id = tid + 256 * i;
            int r = id >> 3, c4 = (id & 7) * 4;
            float4 v = *(float4*)&s_epi[r * 36 + c4];
            *(float4*)(g_h + (size_t)(rowBase + r) * HID + hb + c4) = v;
        }
    }
}

// ---------------------------------------------------------------------------
// GEMM3: q = g_h @ g_w2^T + b2. BM=128, BN=32, 128 thr (4 warps, 64x16), 4 st.
// ---------------------------------------------------------------------------
#define QSTG 10240
#define QSMEM (NS * QSTG)            // 40960

__global__ void __launch_bounds__(128) q_mma_kernel(
    const float* __restrict__ b2, float* __restrict__ q)
{
    extern __shared__ char smem[];
    const uint32_t tiles_u = smem_u32(smem);
    const int tid = threadIdx.x, lane = tid & 31, wid = tid >> 5;
    const int m0w = 64 * (wid & 1), n0w = 16 * (wid >> 1);
    const int rowBase = blockIdx.x * 128;

    const char* aptr[4]; uint32_t aoff[4];
    #pragma unroll
    for (int j = 0; j < 4; j++) {
        int m = (tid + 128 * j) >> 2, c = tid & 3;
        aptr[j] = (const char*)(g_h + (size_t)(rowBase + m) * HID + 4 * c);
        aoff[j] = m * 64 + ((c ^ (m & 3)) << 4);
    }
    const int br = tid >> 2, bc = tid & 3;
    const char* bptr = (const char*)(g_w2 + (size_t)br * HID + 4 * bc);
    const uint32_t boff = 8192 + br * 64 + ((bc ^ (br & 3)) << 4);

    const int a_m  = m0w + (lane & 15);
    const int a_cb = lane >> 4, a_sw = a_m & 3;
    const int b_n  = n0w + (lane & 7) + ((lane & 16) >> 1);
    const int b_cb = (lane >> 3) & 1, b_sw = b_n & 3;

    float acc[4][2][4];
    #pragma unroll
    for (int i = 0; i < 4; i++)
        #pragma unroll
        for (int j = 0; j < 2; j++)
            #pragma unroll
            for (int k = 0; k < 4; k++) acc[i][j][k] = 0.f;

    auto issue = [&](int t) {
        uint32_t base = tiles_u + (t & (NS - 1)) * QSTG;
        size_t ko = (size_t)t * 64;
        #pragma unroll
        for (int j = 0; j < 4; j++) CP16(base + aoff[j], aptr[j] + ko);
        CP16(base + boff, bptr + ko);
        CP_COMMIT();
    };

    issue(0); issue(1); issue(2);
    const int KT = HID / 16;
    for (int t = 0; t < KT; t++) {
        CP_WAIT2();
        __syncthreads();
        const uint32_t Ab = tiles_u + (t & (NS - 1)) * QSTG, Bb = Ab + 8192;
        #pragma unroll
        for (int ks = 0; ks < 2; ks++) {
            uint32_t af[4][4], bf[4];
            #pragma unroll
            for (int mi = 0; mi < 4; mi++)
                ldsm4(af[mi], Ab + (a_m + 16 * mi) * 64 + (((2 * ks + a_cb) ^ a_sw) << 4));
            ldsm4(bf, Bb + b_n * 64 + (((2 * ks + b_cb) ^ b_sw) << 4));
            #pragma unroll
            for (int mi = 0; mi < 4; mi++)
                #pragma unroll
                for (int ni = 0; ni < 2; ni++)
                    mma_tf(acc[mi][ni], af[mi], bf[ni * 2], bf[ni * 2 + 1]);
        }
        if (t + 3 < KT) issue(t + 3); else CP_COMMIT();
    }

    #pragma unroll
    for (int mi = 0; mi < 4; mi++) {
        int r = rowBase + m0w + 16 * mi + (lane >> 2);
        #pragma unroll
        for (int ni = 0; ni < 2; ni++) {
            int cl = n0w + 8 * ni + 2 * (lane & 3);
            float bb0 = __ldg(b2 + cl), bb1 = __ldg(b2 + cl + 1);
            float* d0 = q + (size_t)r * NQ + cl;
            *(float2*)d0 = make_float2(acc[mi][ni][0] + bb0, acc[mi][ni][1] + bb1);
            *(float2*)(d0 + 8 * NQ) = make_float2(acc[mi][ni][2] + bb0, acc[mi][ni][3] + bb1);
        }
    }
}

// ---------------------------------------------------------------------------
extern "C" void kernel_launch(void* const* d_in, const int* in_sizes, int n_in,
                              void* d_out, int out_size)
{
    const float* obs = (const float*)d_in[0];
    const float* act = (const float*)d_in[1];
    const float* hst = (const float*)d_in[2];
    const float* cst = (const float*)d_in[3];
    const float* W1  = (const float*)d_in[4];
    const float* b1  = (const float*)d_in[5];
    const float* Wih = (const float*)d_in[6];
    const float* bih = (const float*)d_in[7];
    const float* Whh = (const float*)d_in[8];
    const float* bhh = (const float*)d_in[9];
    const float* W2  = (const float*)d_in[10];
    const float* b2  = (const float*)d_in[11];
    float* out = (float*)d_out;

    cudaFuncSetAttribute(mma_gemm_kernel<0>,
                         cudaFuncAttributeMaxDynamicSharedMemorySize, GSMEM);
    cudaFuncSetAttribute(mma_gemm_kernel<1>,
                         cudaFuncAttributeMaxDynamicSharedMemorySize, GSMEM);
    cudaFuncSetAttribute(q_mma_kernel,
                         cudaFuncAttributeMaxDynamicSharedMemorySize, QSMEM);

    pack_in_kernel<<<(B_ROWS * 136 + 255) / 256, 256>>>(obs, act);
    conv_w_kernel<<<(EMB * KIN / 4 + 4 * HID * EMB / 4 + NQ * HID / 4 + 255) / 256, 256>>>(
        W1, Wih, W2);
    hvec_kernel<<<256, 256>>>(Whh, hst, bih, bhh);

    // x = relu(g_in @ g_w1^T + b1)
    mma_gemm_kernel<0><<<dim3(EMB / 128, B_ROWS / 128), 256, GSMEM>>>(b1, cst, out);
    // gates + LSTM cell
    mma_gemm_kernel<1><<<dim3(4 * HID / 128, B_ROWS / 128), 256, GSMEM>>>(b1, cst, out);
    // q
    q_mma_kernel<<<B_ROWS / 128, 128, QSMEM>>>(b2, out);
}

// round 11
// speedup vs baseline: 1.7688x; 1.7688x over previous
#include <cuda_runtime.h>
#include <cuda_fp16.h>
#include <cstdint>

// ---------------------------------------------------------------------------
// DRQN fused pipeline (sm_103 base ISA). R11: GEMMs on mma.sync.m16n8k16.f16
// (fp16 mantissa == tf32 mantissa -> same accuracy, 2x K per HMMA, half the
// bytes everywhere). Elementwise math stays fp32. cp.async 4-stage pipeline.
//
// NOTE: __device__ globals are ONLY referenced from device code (GB300 ATS
// silently reads the host shadow if passed as host-side kernel args).
//
//   hvec = W_hh@h + b_ih + b_hh                  (fp32, exact)
//   x    = relu(g_in @ W1^T + b1)                GEMM1 BM128 BN128 fp16
//   gates= x @ Wih^T (gate-interleaved) -> LSTM  GEMM2 BM128 BN128 fp16
//   q    = h @ W2^T + b2                         GEMM3 BM128 BN32  fp16
// Output: [ q (B*32) | h_new[B-1] (512) | c_new[B-1] (512) ]
// ---------------------------------------------------------------------------

#define B_ROWS 32768
#define OBS    512
#define ACT    32
#define KIN    544
#define EMB    512
#define HID    512
#define NQ     32

__device__ __half g_in[(size_t)B_ROWS * KIN];
__device__ __half g_x [(size_t)B_ROWS * EMB];
__device__ __half g_h [(size_t)B_ROWS * HID];
__device__ __half g_w1 [EMB * KIN];
__device__ __half g_wih[4 * HID * EMB];
__device__ __half g_w2 [NQ * HID];
__device__ float  g_hvec[4 * HID];

// ------------------------------ helpers -----------------------------------
__device__ __forceinline__ uint32_t smem_u32(const void* p) {
    uint32_t a;
    asm("{ .reg .u64 t; cvta.to.shared.u64 t, %1; cvt.u32.u64 %0, t; }"
        : "=r"(a) : "l"(p));
    return a;
}
__device__ __forceinline__ uint32_t h2u(float a, float b) {
    __half2 h = __floats2half2_rn(a, b);
    return *(uint32_t*)&h;
}
__device__ __forceinline__ uint2 r4h(float4 v) {      // 4 floats -> 4 halves
    return make_uint2(h2u(v.x, v.y), h2u(v.z, v.w));
}
__device__ __forceinline__ void ldsm4(uint32_t* r, uint32_t addr) {
    asm volatile("ldmatrix.sync.aligned.m8n8.x4.shared.b16 {%0,%1,%2,%3}, [%4];"
                 : "=r"(r[0]), "=r"(r[1]), "=r"(r[2]), "=r"(r[3]) : "r"(addr));
}
__device__ __forceinline__ void mma_h(float* c, const uint32_t* a,
                                      uint32_t b0, uint32_t b1) {
    asm volatile(
        "mma.sync.aligned.m16n8k16.row.col.f32.f16.f16.f32 "
        "{%0,%1,%2,%3}, {%4,%5,%6,%7}, {%8,%9}, {%0,%1,%2,%3};"
        : "+f"(c[0]), "+f"(c[1]), "+f"(c[2]), "+f"(c[3])
        : "r"(a[0]), "r"(a[1]), "r"(a[2]), "r"(a[3]), "r"(b0), "r"(b1));
}
#define CP16(dst, src) asm volatile("cp.async.cg.shared.global [%0], [%1], 16;" :: "r"(dst), "l"(src) : "memory")
#define CP_COMMIT()    asm volatile("cp.async.commit_group;" ::: "memory")
#define CP_WAIT2()     asm volatile("cp.async.wait_group 2;" ::: "memory")

__device__ __forceinline__ float sigmoidf_(float x) {
    return __fdividef(1.f, 1.f + __expf(-x));
}
__device__ __forceinline__ float tanhf_(float x) {
    return __fdividef(2.f, 1.f + __expf(-2.f * x)) - 1.f;
}

// ---------------------------------------------------------------------------
// Pre-pass: pack [obs|act] -> fp16 g_in; fp16 weight copies.
// ---------------------------------------------------------------------------
__global__ void __launch_bounds__(256) pack_in_kernel(
    const float* __restrict__ obs, const float* __restrict__ act)
{
    int id = blockIdx.x * 256 + threadIdx.x;           // over B_ROWS*136 float4
    if (id >= B_ROWS * 136) return;
    int b = id / 136, c4 = (id - b * 136) * 4;
    float4 v = (c4 < OBS) ? *(const float4*)(obs + (size_t)b * OBS + c4)
                          : *(const float4*)(act + (size_t)b * ACT + (c4 - OBS));
    *(uint2*)(g_in + (size_t)b * KIN + c4) = r4h(v);
}
__global__ void __launch_bounds__(256) conv_w_kernel(
    const float* __restrict__ W1, const float* __restrict__ Wih,
    const float* __restrict__ W2)
{
    int id = blockIdx.x * 256 + threadIdx.x;           // float4 index
    const int N1 = EMB * KIN / 4, N2 = N1 + 4 * HID * EMB / 4;
    const int N3 = N2 + NQ * HID / 4;
    if (id < N1)      *(uint2*)(g_w1  + 4 * id)        = r4h(*(const float4*)(W1  + 4 * id));
    else if (id < N2) *(uint2*)(g_wih + 4 * (id - N1)) = r4h(*(const float4*)(Wih + 4 * (size_t)(id - N1)));
    else if (id < N3) *(uint2*)(g_w2  + 4 * (id - N2)) = r4h(*(const float4*)(W2  + 4 * (id - N2)));
}

// ---------------------------------------------------------------------------
// K0: hvec[n] = dot(W_hh[n,:], h) + b_ih[n] + b_hh[n]   (exact fp32)
// ---------------------------------------------------------------------------
__global__ void __launch_bounds__(256) hvec_kernel(
    const float* __restrict__ Whh, const float* __restrict__ h,
    const float* __restrict__ bih, const float* __restrict__ bhh)
{
    int w    = (blockIdx.x * blockDim.x + threadIdx.x) >> 5;
    int lane = threadIdx.x & 31;
    if (w >= 4 * HID) return;
    const float* row = Whh + (size_t)w * HID;
    float s = 0.f;
    #pragma unroll
    for (int k = 0; k < HID; k += 32) s += row[k + lane] * h[k + lane];
    #pragma unroll
    for (int o = 16; o > 0; o >>= 1) s += __shfl_xor_sync(0xffffffffu, s, o);
    if (lane == 0) g_hvec[w] = s + bih[w] + bhh[w];
}

// ---------------------------------------------------------------------------
// GEMM: BM=128, BN=128, BK=32(fp16), 256 thr (8 warps, warp tile 64x32),
// 4 stages, 2 CTAs/SM. Smem row = 64B = 32 halves (same swizzle as tf32).
// MODE 0: relu GEMM1, grid (4, 256). MODE 1: gate-interleaved + LSTM,
// grid (16, 256), 32 hid/CTA.
// ---------------------------------------------------------------------------
#define NS 4
#define STG 16384
#define GSMEM (2048 + NS * STG)      // 67584

template <int MODE>
__global__ void __launch_bounds__(256, 2) mma_gemm_kernel(
    const float* __restrict__ b1, const float* __restrict__ cell,
    float* __restrict__ out)
{
    constexpr int KA = (MODE == 0) ? KIN : EMB;        // in halves
    constexpr int KT = KA / 32;
    const __half* gA = (MODE == 0) ? g_in : g_x;
    const __half* gB = (MODE == 0) ? g_w1 : g_wih;

    extern __shared__ char smem[];
    float* s_aux = (float*)smem;
    char*  tiles = smem + 2048;
    float* s_epi = (float*)tiles;
    const uint32_t tiles_u = smem_u32(tiles);

    const int tid = threadIdx.x, lane = tid & 31, wid = tid >> 5;
    const int m0w = 64 * (wid & 1), n0w = 32 * (wid >> 1);
    const int rowBase = blockIdx.y * 128;
    const int colBase = blockIdx.x * 128;   // MODE 0
    const int hb      = blockIdx.x * 32;    // MODE 1

    if (MODE == 0) {
        if (tid < 128) s_aux[tid] = b1[colBase + tid];
    } else {
        if (tid < 32)  s_aux[tid] = cell[hb + tid];
        if (tid < 128) s_aux[32 + tid] = g_hvec[((tid >> 5) << 9) + hb + (tid & 31)];
    }

    // cp.async: 512 chunks/tile (128 rows x 4x16B), 2 A + 2 B per thread.
    const char* aptr[2]; uint32_t aoff[2];
    const char* bptr[2]; uint32_t boff[2];
    #pragma unroll
    for (int j = 0; j < 2; j++) {
        int m = (tid + 256 * j) >> 2, c = tid & 3;     // chunk c -> k = 8c halves
        aptr[j] = (const char*)(gA + (size_t)(rowBase + m) * KA + 8 * c);
        aoff[j] = m * 64 + ((c ^ (m & 3)) << 4);
        if (MODE == 0) {
            bptr[j] = (const char*)(gB + (size_t)(colBase + m) * KA + 8 * c);
        } else {
            int wr = ((m & 3) << 9) + hb + (m >> 2);    // 512*gate + hid
            bptr[j] = (const char*)(gB + (size_t)wr * EMB + 8 * c);
        }
        boff[j] = 8192 + aoff[j];
    }

    // ldmatrix lane constants (identical geometry; ks selects k16 half)
    const int a_m  = m0w + (lane & 15);
    const int a_cb = lane >> 4, a_sw = a_m & 3;
    const int b_n  = n0w + (lane & 7) + ((lane & 16) >> 1);
    const int b_cb = (lane >> 3) & 1, b_sw = b_n & 3;

    float acc[4][4][4];
    #pragma unroll
    for (int i = 0; i < 4; i++)
        #pragma unroll
        for (int j = 0; j < 4; j++)
            #pragma unroll
            for (int k = 0; k < 4; k++) acc[i][j][k] = 0.f;

    auto issue = [&](int t) {
        uint32_t base = tiles_u + (t & (NS - 1)) * STG;
        size_t ko = (size_t)t * 64;                    // 32 halves = 64 bytes
        #pragma unroll
        for (int j = 0; j < 2; j++) CP16(base + aoff[j], aptr[j] + ko);
        #pragma unroll
        for (int j = 0; j < 2; j++) CP16(base + boff[j], bptr[j] + ko);
        CP_COMMIT();
    };
    auto compute = [&](int s) {
        const uint32_t Ab = tiles_u + s * STG, Bb = Ab + 8192;
        #pragma unroll
        for (int ks = 0; ks < 2; ks++) {               // 2 x k16 per stage
            uint32_t af[4][4], bf[2][4];
            #pragma unroll
            for (int mi = 0; mi < 4; mi++)
                ldsm4(af[mi], Ab + (a_m + 16 * mi) * 64 + (((2 * ks + a_cb) ^ a_sw) << 4));
            #pragma unroll
            for (int p = 0; p < 2; p++)
                ldsm4(bf[p], Bb + (b_n + 16 * p) * 64 + (((2 * ks + b_cb) ^ b_sw) << 4));
            #pragma unroll
            for (int mi = 0; mi < 4; mi++)
                #pragma unroll
                for (int ni = 0; ni < 4; ni++)
                    mma_h(acc[mi][ni], af[mi],
                          bf[ni >> 1][(ni & 1) * 2], bf[ni >> 1][(ni & 1) * 2 + 1]);
        }
    };

    issue(0); issue(1); issue(2);
    for (int t = 0; t < KT; t++) {
        CP_WAIT2();
        __syncthreads();
        compute(t & (NS - 1));
        if (t + 3 < KT) issue(t + 3); else CP_COMMIT();   // keep group count
    }

    // ---------------- epilogue ----------------
    if (MODE == 0) {
        #pragma unroll
        for (int mi = 0; mi < 4; mi++) {
            int r = rowBase + m0w + 16 * mi + (lane >> 2);
            #pragma unroll
            for (int ni = 0; ni < 4; ni++) {
                int cl = n0w + 8 * ni + 2 * (lane & 3);
                __half* d0 = g_x + (size_t)r * EMB + colBase + cl;
                *(uint32_t*)d0 = h2u(fmaxf(acc[mi][ni][0] + s_aux[cl], 0.f),
                                     fmaxf(acc[mi][ni][1] + s_aux[cl + 1], 0.f));
                *(uint32_t*)(d0 + 8 * EMB) =
                             h2u(fmaxf(acc[mi][ni][2] + s_aux[cl], 0.f),
                                 fmaxf(acc[mi][ni][3] + s_aux[cl + 1], 0.f));
            }
        }
    } else {
        __syncthreads();                        // tiles -> s_epi reuse
        #pragma unroll
        for (int mi = 0; mi < 4; mi++) {
            #pragma unroll
            for (int ni = 0; ni < 4; ni++) {
                float c0 = acc[mi][ni][0], c1 = acc[mi][ni][1];
                float c2 = acc[mi][ni][2], c3 = acc[mi][ni][3];
                float e0 = __shfl_xor_sync(0xffffffffu, c0, 1);
                float e1 = __shfl_xor_sync(0xffffffffu, c1, 1);
                float e2 = __shfl_xor_sync(0xffffffffu, c2, 1);
                float e3 = __shfl_xor_sync(0xffffffffu, c3, 1);
                bool ev = !(lane & 1);
                int rl = m0w + 16 * mi + (lane >> 2) + (ev ? 0 : 8);
                float gi = ev ? c0 : e2;
                float gf = ev ? c1 : e3;
                float gg = ev ? e0 : c2;
                float go = ev ? e1 : c3;
                int hl = (n0w >> 2) + 2 * ni + ((lane & 3) >> 1);
                float iv = sigmoidf_(gi + s_aux[32 + hl]);
                float fv = sigmoidf_(gf + s_aux[64 + hl]);
                float gv = tanhf_   (gg + s_aux[96 + hl]);
                float ov = sigmoidf_(go + s_aux[128 + hl]);
                float cn = fv * s_aux[hl] + iv * gv;
                float hn = ov * tanhf_(cn);
                s_epi[rl * 36 + hl] = hn;
                if (rowBase + rl == B_ROWS - 1) {
                    out[(size_t)B_ROWS * NQ + hb + hl]       = hn;
                    out[(size_t)B_ROWS * NQ + HID + hb + hl] = cn;
                }
            }
        }
        __syncthreads();
        #pragma unroll
        for (int i = 0; i < 4; i++) {
            int id = tid + 256 * i;
            int r = id >> 3, c4 = (id & 7) * 4;
            float4 v = *(float4*)&s_epi[r * 36 + c4];
            *(uint2*)(g_h + (size_t)(rowBase + r) * HID + hb + c4) = r4h(v);
        }
    }
}

// ---------------------------------------------------------------------------
// GEMM3: q = g_h @ g_w2^T + b2. BM=128, BN=32, 128 thr (4 warps, 64x16), 4 st.
// ---------------------------------------------------------------------------
#define QSTG 10240
#define QSMEM (NS * QSTG)            // 40960

__global__ void __launch_bounds__(128) q_mma_kernel(
    const float* __restrict__ b2, float* __restrict__ q)
{
    extern __shared__ char smem[];
    const uint32_t tiles_u = smem_u32(smem);
    const int tid = threadIdx.x, lane = tid & 31, wid = tid >> 5;
    const int m0w = 64 * (wid & 1), n0w = 16 * (wid >> 1);
    const int rowBase = blockIdx.x * 128;

    const char* aptr[4]; uint32_t aoff[4];
    #pragma unroll
    for (int j = 0; j < 4; j++) {
        int m = (tid + 128 * j) >> 2, c = tid & 3;
        aptr[j] = (const char*)(g_h + (size_t)(rowBase + m) * HID + 8 * c);
        aoff[j] = m * 64 + ((c ^ (m & 3)) << 4);
    }
    const int br = tid >> 2, bc = tid & 3;
    const char* bptr = (const char*)(g_w2 + (size_t)br * HID + 8 * bc);
    const uint32_t boff = 8192 + br * 64 + ((bc ^ (br & 3)) << 4);

    const int a_m  = m0w + (lane & 15);
    const int a_cb = lane >> 4, a_sw = a_m & 3;
    const int b_n  = n0w + (lane & 7) + ((lane & 16) >> 1);
    const int b_cb = (lane >> 3) & 1, b_sw = b_n & 3;

    float acc[4][2][4];
    #pragma unroll
    for (int i = 0; i < 4; i++)
        #pragma unroll
        for (int j = 0; j < 2; j++)
            #pragma unroll
            for (int k = 0; k < 4; k++) acc[i][j][k] = 0.f;

    auto issue = [&](int t) {
        uint32_t base = tiles_u + (t & (NS - 1)) * QSTG;
        size_t ko = (size_t)t * 64;
        #pragma unroll
        for (int j = 0; j < 4; j++) CP16(base + aoff[j], aptr[j] + ko);
        CP16(base + boff, bptr + ko);
        CP_COMMIT();
    };

    issue(0); issue(1); issue(2);
    const int KT = HID / 32;
    for (int t = 0; t < KT; t++) {
        CP_WAIT2();
        __syncthreads();
        const uint32_t Ab = tiles_u + (t & (NS - 1)) * QSTG, Bb = Ab + 8192;
        #pragma unroll
        for (int ks = 0; ks < 2; ks++) {
            uint32_t af[4][4], bf[4];
            #pragma unroll
            for (int mi = 0; mi < 4; mi++)
                ldsm4(af[mi], Ab + (a_m + 16 * mi) * 64 + (((2 * ks + a_cb) ^ a_sw) << 4));
            ldsm4(bf, Bb + b_n * 64 + (((2 * ks + b_cb) ^ b_sw) << 4));
            #pragma unroll
            for (int mi = 0; mi < 4; mi++)
                #pragma unroll
                for (int ni = 0; ni < 2; ni++)
                    mma_h(acc[mi][ni], af[mi], bf[ni * 2], bf[ni * 2 + 1]);
        }
        if (t + 3 < KT) issue(t + 3); else CP_COMMIT();
    }

    #pragma unroll
    for (int mi = 0; mi < 4; mi++) {
        int r = rowBase + m0w + 16 * mi + (lane >> 2);
        #pragma unroll
        for (int ni = 0; ni < 2; ni++) {
            int cl = n0w + 8 * ni + 2 * (lane & 3);
            float bb0 = __ldg(b2 + cl), bb1 = __ldg(b2 + cl + 1);
            float* d0 = q + (size_t)r * NQ + cl;
            *(float2*)d0 = make_float2(acc[mi][ni][0] + bb0, acc[mi][ni][1] + bb1);
            *(float2*)(d0 + 8 * NQ) = make_float2(acc[mi][ni][2] + bb0, acc[mi][ni][3] + bb1);
        }
    }
}

// ---------------------------------------------------------------------------
extern "C" void kernel_launch(void* const* d_in, const int* in_sizes, int n_in,
                              void* d_out, int out_size)
{
    const float* obs = (const float*)d_in[0];
    const float* act = (const float*)d_in[1];
    const float* hst = (const float*)d_in[2];
    const float* cst = (const float*)d_in[3];
    const float* W1  = (const float*)d_in[4];
    const float* b1  = (const float*)d_in[5];
    const float* Wih = (const float*)d_in[6];
    const float* bih = (const float*)d_in[7];
    const float* Whh = (const float*)d_in[8];
    const float* bhh = (const float*)d_in[9];
    const float* W2  = (const float*)d_in[10];
    const float* b2  = (const float*)d_in[11];
    float* out = (float*)d_out;

    cudaFuncSetAttribute(mma_gemm_kernel<0>,
                         cudaFuncAttributeMaxDynamicSharedMemorySize, GSMEM);
    cudaFuncSetAttribute(mma_gemm_kernel<1>,
                         cudaFuncAttributeMaxDynamicSharedMemorySize, GSMEM);
    cudaFuncSetAttribute(q_mma_kernel,
                         cudaFuncAttributeMaxDynamicSharedMemorySize, QSMEM);

    pack_in_kernel<<<(B_ROWS * 136 + 255) / 256, 256>>>(obs, act);
    conv_w_kernel<<<(EMB * KIN / 4 + 4 * HID * EMB / 4 + NQ * HID / 4 + 255) / 256, 256>>>(
        W1, Wih, W2);
    hvec_kernel<<<256, 256>>>(Whh, hst, bih, bhh);

    // x = relu(g_in @ g_w1^T + b1)
    mma_gemm_kernel<0><<<dim3(EMB / 128, B_ROWS / 128), 256, GSMEM>>>(b1, cst, out);
    // gates + LSTM cell
    mma_gemm_kernel<1><<<dim3(4 * HID / 128, B_ROWS / 128), 256, GSMEM>>>(b1, cst, out);
    // q
    q_mma_kernel<<<B_ROWS / 128, 128, QSMEM>>>(b2, out);
}

// round 12
// speedup vs baseline: 1.7853x; 1.0093x over previous
#include <cuda_runtime.h>
#include <cuda_fp16.h>
#include <cstdint>

// ---------------------------------------------------------------------------
// DRQN fused pipeline (sm_103 base ISA). R12: fp16 mma.sync.m16n8k16 with
// 64x64 warp tiles (BN=256, 8 warps) to cut LDSM/smem traffic per MMA 1.5x
// vs R11's 64x32. cp.async 4-stage pipeline; elementwise math fp32.
//
// NOTE: __device__ globals are ONLY referenced from device code (GB300 ATS
// silently reads the host shadow if passed as host-side kernel args).
//
//   hvec = W_hh@h + b_ih + b_hh                  (fp32, exact)
//   x    = relu(g_in @ W1^T + b1)                GEMM1 BM128 BN256 fp16
//   gates= x @ Wih^T (gate-interleaved) -> LSTM  GEMM2 BM128 BN256 fp16
//   q    = h @ W2^T + b2                         GEMM3 BM128 BN32  fp16
// Output: [ q (B*32) | h_new[B-1] (512) | c_new[B-1] (512) ]
// ---------------------------------------------------------------------------

#define B_ROWS 32768
#define OBS    512
#define ACT    32
#define KIN    544
#define EMB    512
#define HID    512
#define NQ     32

__device__ __half g_in[(size_t)B_ROWS * KIN];
__device__ __half g_x [(size_t)B_ROWS * EMB];
__device__ __half g_h [(size_t)B_ROWS * HID];
__device__ __half g_w1 [EMB * KIN];
__device__ __half g_wih[4 * HID * EMB];
__device__ __half g_w2 [NQ * HID];
__device__ float  g_hvec[4 * HID];

// ------------------------------ helpers -----------------------------------
__device__ __forceinline__ uint32_t smem_u32(const void* p) {
    uint32_t a;
    asm("{ .reg .u64 t; cvta.to.shared.u64 t, %1; cvt.u32.u64 %0, t; }"
        : "=r"(a) : "l"(p));
    return a;
}
__device__ __forceinline__ uint32_t h2u(float a, float b) {
    __half2 h = __floats2half2_rn(a, b);
    return *(uint32_t*)&h;
}
__device__ __forceinline__ uint2 r4h(float4 v) {      // 4 floats -> 4 halves
    return make_uint2(h2u(v.x, v.y), h2u(v.z, v.w));
}
__device__ __forceinline__ void ldsm4(uint32_t* r, uint32_t addr) {
    asm volatile("ldmatrix.sync.aligned.m8n8.x4.shared.b16 {%0,%1,%2,%3}, [%4];"
                 : "=r"(r[0]), "=r"(r[1]), "=r"(r[2]), "=r"(r[3]) : "r"(addr));
}
__device__ __forceinline__ void mma_h(float* c, const uint32_t* a,
                                      uint32_t b0, uint32_t b1) {
    asm volatile(
        "mma.sync.aligned.m16n8k16.row.col.f32.f16.f16.f32 "
        "{%0,%1,%2,%3}, {%4,%5,%6,%7}, {%8,%9}, {%0,%1,%2,%3};"
        : "+f"(c[0]), "+f"(c[1]), "+f"(c[2]), "+f"(c[3])
        : "r"(a[0]), "r"(a[1]), "r"(a[2]), "r"(a[3]), "r"(b0), "r"(b1));
}
#define CP16(dst, src) asm volatile("cp.async.cg.shared.global [%0], [%1], 16;" :: "r"(dst), "l"(src) : "memory")
#define CP_COMMIT()    asm volatile("cp.async.commit_group;" ::: "memory")
#define CP_WAIT2()     asm volatile("cp.async.wait_group 2;" ::: "memory")

__device__ __forceinline__ float sigmoidf_(float x) {
    return __fdividef(1.f, 1.f + __expf(-x));
}
__device__ __forceinline__ float tanhf_(float x) {
    return __fdividef(2.f, 1.f + __expf(-2.f * x)) - 1.f;
}

// ---------------------------------------------------------------------------
// Pre-pass: pack [obs|act] -> fp16 g_in; fp16 weight copies.
// ---------------------------------------------------------------------------
__global__ void __launch_bounds__(256) pack_in_kernel(
    const float* __restrict__ obs, const float* __restrict__ act)
{
    int id = blockIdx.x * 256 + threadIdx.x;           // over B_ROWS*136 float4
    if (id >= B_ROWS * 136) return;
    int b = id / 136, c4 = (id - b * 136) * 4;
    float4 v = (c4 < OBS) ? *(const float4*)(obs + (size_t)b * OBS + c4)
                          : *(const float4*)(act + (size_t)b * ACT + (c4 - OBS));
    *(uint2*)(g_in + (size_t)b * KIN + c4) = r4h(v);
}
__global__ void __launch_bounds__(256) conv_w_kernel(
    const float* __restrict__ W1, const float* __restrict__ Wih,
    const float* __restrict__ W2)
{
    int id = blockIdx.x * 256 + threadIdx.x;           // float4 index
    const int N1 = EMB * KIN / 4, N2 = N1 + 4 * HID * EMB / 4;
    const int N3 = N2 + NQ * HID / 4;
    if (id < N1)      *(uint2*)(g_w1  + 4 * id)        = r4h(*(const float4*)(W1  + 4 * id));
    else if (id < N2) *(uint2*)(g_wih + 4 * (id - N1)) = r4h(*(const float4*)(Wih + 4 * (size_t)(id - N1)));
    else if (id < N3) *(uint2*)(g_w2  + 4 * (id - N2)) = r4h(*(const float4*)(W2  + 4 * (id - N2)));
}

// ---------------------------------------------------------------------------
// K0: hvec[n] = dot(W_hh[n,:], h) + b_ih[n] + b_hh[n]   (exact fp32)
// ---------------------------------------------------------------------------
__global__ void __launch_bounds__(256) hvec_kernel(
    const float* __restrict__ Whh, const float* __restrict__ h,
    const float* __restrict__ bih, const float* __restrict__ bhh)
{
    int w    = (blockIdx.x * blockDim.x + threadIdx.x) >> 5;
    int lane = threadIdx.x & 31;
    if (w >= 4 * HID) return;
    const float* row = Whh + (size_t)w * HID;
    float s = 0.f;
    #pragma unroll
    for (int k = 0; k < HID; k += 32) s += row[k + lane] * h[k + lane];
    #pragma unroll
    for (int o = 16; o > 0; o >>= 1) s += __shfl_xor_sync(0xffffffffu, s, o);
    if (lane == 0) g_hvec[w] = s + bih[w] + bhh[w];
}

// ---------------------------------------------------------------------------
// GEMM: BM=128, BN=256, BK=32(fp16), 256 thr (8 warps, warp tile 64x64),
// 4 stages, 1 CTA/SM. Smem row = 64B = 32 halves, swizzled.
// MODE 0: relu GEMM1, grid (2, 256). MODE 1: gate-interleaved + LSTM,
// grid (8, 256), 64 hid/CTA.
// smem: [0,2048) aux | 4 stages x (A 8K | B 16K); MODE1 epilogue reuses tiles.
// ---------------------------------------------------------------------------
#define NS 4
#define STG 24576
#define GSMEM (2048 + NS * STG)      // 100352

template <int MODE>
__global__ void __launch_bounds__(256, 1) mma_gemm_kernel(
    const float* __restrict__ b1, const float* __restrict__ cell,
    float* __restrict__ out)
{
    constexpr int KA = (MODE == 0) ? KIN : EMB;        // in halves
    constexpr int KT = KA / 32;
    const __half* gA = (MODE == 0) ? g_in : g_x;
    const __half* gB = (MODE == 0) ? g_w1 : g_wih;

    extern __shared__ char smem[];
    float* s_aux = (float*)smem;
    char*  tiles = smem + 2048;
    float* s_epi = (float*)tiles;
    const uint32_t tiles_u = smem_u32(tiles);

    const int tid = threadIdx.x, lane = tid & 31, wid = tid >> 5;
    const int m0w = 64 * (wid & 1), n0w = 64 * (wid >> 1);
    const int rowBase = blockIdx.y * 128;
    const int colBase = blockIdx.x * 256;   // MODE 0
    const int hb      = blockIdx.x * 64;    // MODE 1

    if (MODE == 0) {
        s_aux[tid] = b1[colBase + tid];
    } else {
        if (tid < 64) s_aux[tid] = cell[hb + tid];
        s_aux[64 + tid] = g_hvec[((tid >> 6) << 9) + hb + (tid & 63)];
    }

    // cp.async: A 512 chunks (2/thr), B 1024 chunks (4/thr); 16B chunks.
    const char* aptr[2]; uint32_t aoff[2];
    #pragma unroll
    for (int j = 0; j < 2; j++) {
        int m = (tid + 256 * j) >> 2, c = tid & 3;     // chunk c -> k = 8c halves
        aptr[j] = (const char*)(gA + (size_t)(rowBase + m) * KA + 8 * c);
        aoff[j] = m * 64 + ((c ^ (m & 3)) << 4);
    }
    const char* bptr[4]; uint32_t boff[4];
    #pragma unroll
    for (int j = 0; j < 4; j++) {
        int id = tid + 256 * j;
        int r = id >> 2, c = id & 3;
        if (MODE == 0) {
            bptr[j] = (const char*)(gB + (size_t)(colBase + r) * KA + 8 * c);
        } else {
            int wr = ((r & 3) << 9) + hb + (r >> 2);    // 512*gate + hid
            bptr[j] = (const char*)(gB + (size_t)wr * EMB + 8 * c);
        }
        boff[j] = 8192 + r * 64 + ((c ^ (r & 3)) << 4);
    }

    // ldmatrix lane constants
    const int a_m  = m0w + (lane & 15);
    const int a_cb = lane >> 4, a_sw = a_m & 3;
    const int b_n  = n0w + (lane & 7) + ((lane & 16) >> 1);
    const int b_cb = (lane >> 3) & 1, b_sw = b_n & 3;

    float acc[4][8][4];
    #pragma unroll
    for (int i = 0; i < 4; i++)
        #pragma unroll
        for (int j = 0; j < 8; j++)
            #pragma unroll
            for (int k = 0; k < 4; k++) acc[i][j][k] = 0.f;

    auto issue = [&](int t) {
        uint32_t base = tiles_u + (t & (NS - 1)) * STG;
        size_t ko = (size_t)t * 64;                    // 32 halves = 64 bytes
        #pragma unroll
        for (int j = 0; j < 2; j++) CP16(base + aoff[j], aptr[j] + ko);
        #pragma unroll
        for (int j = 0; j < 4; j++) CP16(base + boff[j], bptr[j] + ko);
        CP_COMMIT();
    };
    auto compute = [&](int s) {
        const uint32_t Ab = tiles_u + s * STG, Bb = Ab + 8192;
        #pragma unroll
        for (int ks = 0; ks < 2; ks++) {               // 2 x k16 per stage
            uint32_t af[4][4], bf[4][4];
            #pragma unroll
            for (int mi = 0; mi < 4; mi++)
                ldsm4(af[mi], Ab + (a_m + 16 * mi) * 64 + (((2 * ks + a_cb) ^ a_sw) << 4));
            #pragma unroll
            for (int p = 0; p < 4; p++)
                ldsm4(bf[p], Bb + (b_n + 16 * p) * 64 + (((2 * ks + b_cb) ^ b_sw) << 4));
            #pragma unroll
            for (int mi = 0; mi < 4; mi++)
                #pragma unroll
                for (int ni = 0; ni < 8; ni++)
                    mma_h(acc[mi][ni], af[mi],
                          bf[ni >> 1][(ni & 1) * 2], bf[ni >> 1][(ni & 1) * 2 + 1]);
        }
    };

    issue(0); issue(1); issue(2);
    for (int t = 0; t < KT; t++) {
        CP_WAIT2();
        __syncthreads();
        compute(t & (NS - 1));
        if (t + 3 < KT) issue(t + 3); else CP_COMMIT();   // keep group count
    }

    // ---------------- epilogue ----------------
    if (MODE == 0) {
        #pragma unroll
        for (int mi = 0; mi < 4; mi++) {
            int r = rowBase + m0w + 16 * mi + (lane >> 2);
            #pragma unroll
            for (int ni = 0; ni < 8; ni++) {
                int cl = n0w + 8 * ni + 2 * (lane & 3);
                __half* d0 = g_x + (size_t)r * EMB + colBase + cl;
                *(uint32_t*)d0 = h2u(fmaxf(acc[mi][ni][0] + s_aux[cl], 0.f),
                                     fmaxf(acc[mi][ni][1] + s_aux[cl + 1], 0.f));
                *(uint32_t*)(d0 + 8 * EMB) =
                             h2u(fmaxf(acc[mi][ni][2] + s_aux[cl], 0.f),
                                 fmaxf(acc[mi][ni][3] + s_aux[cl + 1], 0.f));
            }
        }
    } else {
        __syncthreads();                        // tiles -> s_epi reuse
        #pragma unroll
        for (int mi = 0; mi < 4; mi++) {
            #pragma unroll
            for (int ni = 0; ni < 8; ni++) {
                float c0 = acc[mi][ni][0], c1 = acc[mi][ni][1];
                float c2 = acc[mi][ni][2], c3 = acc[mi][ni][3];
                float e0 = __shfl_xor_sync(0xffffffffu, c0, 1);
                float e1 = __shfl_xor_sync(0xffffffffu, c1, 1);
                float e2 = __shfl_xor_sync(0xffffffffu, c2, 1);
                float e3 = __shfl_xor_sync(0xffffffffu, c3, 1);
                bool ev = !(lane & 1);
                int rl = m0w + 16 * mi + (lane >> 2) + (ev ? 0 : 8);
                float gi = ev ? c0 : e2;
                float gf = ev ? c1 : e3;
                float gg = ev ? e0 : c2;
                float go = ev ? e1 : c3;
                int hl = (n0w >> 2) + 2 * ni + ((lane & 3) >> 1);
                float iv = sigmoidf_(gi + s_aux[64 + hl]);
                float fv = sigmoidf_(gf + s_aux[128 + hl]);
                float gv = tanhf_   (gg + s_aux[192 + hl]);
                float ov = sigmoidf_(go + s_aux[256 + hl]);
                float cn = fv * s_aux[hl] + iv * gv;
                float hn = ov * tanhf_(cn);
                s_epi[rl * 68 + hl] = hn;
                if (rowBase + rl == B_ROWS - 1) {
                    out[(size_t)B_ROWS * NQ + hb + hl]       = hn;
                    out[(size_t)B_ROWS * NQ + HID + hb + hl] = cn;
                }
            }
        }
        __syncthreads();
        #pragma unroll
        for (int i = 0; i < 8; i++) {
            int id = tid + 256 * i;
            int r = id >> 4, c4 = (id & 15) * 4;
            float4 v = *(float4*)&s_epi[r * 68 + c4];
            *(uint2*)(g_h + (size_t)(rowBase + r) * HID + hb + c4) = r4h(v);
        }
    }
}

// ---------------------------------------------------------------------------
// GEMM3: q = g_h @ g_w2^T + b2. BM=128, BN=32, 128 thr (4 warps, 64x16), 4 st.
// ---------------------------------------------------------------------------
#define QSTG 10240
#define QSMEM (NS * QSTG)            // 40960

__global__ void __launch_bounds__(128) q_mma_kernel(
    const float* __restrict__ b2, float* __restrict__ q)
{
    extern __shared__ char smem[];
    const uint32_t tiles_u = smem_u32(smem);
    const int tid = threadIdx.x, lane = tid & 31, wid = tid >> 5;
    const int m0w = 64 * (wid & 1), n0w = 16 * (wid >> 1);
    const int rowBase = blockIdx.x * 128;

    const char* aptr[4]; uint32_t aoff[4];
    #pragma unroll
    for (int j = 0; j < 4; j++) {
        int m = (tid + 128 * j) >> 2, c = tid & 3;
        aptr[j] = (const char*)(g_h + (size_t)(rowBase + m) * HID + 8 * c);
        aoff[j] = m * 64 + ((c ^ (m & 3)) << 4);
    }
    const int br = tid >> 2, bc = tid & 3;
    const char* bptr = (const char*)(g_w2 + (size_t)br * HID + 8 * bc);
    const uint32_t boff = 8192 + br * 64 + ((bc ^ (br & 3)) << 4);

    const int a_m  = m0w + (lane & 15);
    const int a_cb = lane >> 4, a_sw = a_m & 3;
    const int b_n  = n0w + (lane & 7) + ((lane & 16) >> 1);
    const int b_cb = (lane >> 3) & 1, b_sw = b_n & 3;

    float acc[4][2][4];
    #pragma unroll
    for (int i = 0; i < 4; i++)
        #pragma unroll
        for (int j = 0; j < 2; j++)
            #pragma unroll
            for (int k = 0; k < 4; k++) acc[i][j][k] = 0.f;

    auto issue = [&](int t) {
        uint32_t base = tiles_u + (t & (NS - 1)) * QSTG;
        size_t ko = (size_t)t * 64;
        #pragma unroll
        for (int j = 0; j < 4; j++) CP16(base + aoff[j], aptr[j] + ko);
        CP16(base + boff, bptr + ko);
        CP_COMMIT();
    };

    issue(0); issue(1); issue(2);
    const int KT = HID / 32;
    for (int t = 0; t < KT; t++) {
        CP_WAIT2();
        __syncthreads();
        const uint32_t Ab = tiles_u + (t & (NS - 1)) * QSTG, Bb = Ab + 8192;
        #pragma unroll
        for (int ks = 0; ks < 2; ks++) {
            uint32_t af[4][4], bf[4];
            #pragma unroll
            for (int mi = 0; mi < 4; mi++)
                ldsm4(af[mi], Ab + (a_m + 16 * mi) * 64 + (((2 * ks + a_cb) ^ a_sw) << 4));
            ldsm4(bf, Bb + b_n * 64 + (((2 * ks + b_cb) ^ b_sw) << 4));
            #pragma unroll
            for (int mi = 0; mi < 4; mi++)
                #pragma unroll
                for (int ni = 0; ni < 2; ni++)
                    mma_h(acc[mi][ni], af[mi], bf[ni * 2], bf[ni * 2 + 1]);
        }
        if (t + 3 < KT) issue(t + 3); else CP_COMMIT();
    }

    #pragma unroll
    for (int mi = 0; mi < 4; mi++) {
        int r = rowBase + m0w + 16 * mi + (lane >> 2);
        #pragma unroll
        for (int ni = 0; ni < 2; ni++) {
            int cl = n0w + 8 * ni + 2 * (lane & 3);
            float bb0 = __ldg(b2 + cl), bb1 = __ldg(b2 + cl + 1);
            float* d0 = q + (size_t)r * NQ + cl;
            *(float2*)d0 = make_float2(acc[mi][ni][0] + bb0, acc[mi][ni][1] + bb1);
            *(float2*)(d0 + 8 * NQ) = make_float2(acc[mi][ni][2] + bb0, acc[mi][ni][3] + bb1);
        }
    }
}

// ---------------------------------------------------------------------------
extern "C" void kernel_launch(void* const* d_in, const int* in_sizes, int n_in,
                              void* d_out, int out_size)
{
    const float* obs = (const float*)d_in[0];
    const float* act = (const float*)d_in[1];
    const float* hst = (const float*)d_in[2];
    const float* cst = (const float*)d_in[3];
    const float* W1  = (const float*)d_in[4];
    const float* b1  = (const float*)d_in[5];
    const float* Wih = (const float*)d_in[6];
    const float* bih = (const float*)d_in[7];
    const float* Whh = (const float*)d_in[8];
    const float* bhh = (const float*)d_in[9];
    const float* W2  = (const float*)d_in[10];
    const float* b2  = (const float*)d_in[11];
    float* out = (float*)d_out;

    cudaFuncSetAttribute(mma_gemm_kernel<0>,
                         cudaFuncAttributeMaxDynamicSharedMemorySize, GSMEM);
    cudaFuncSetAttribute(mma_gemm_kernel<1>,
                         cudaFuncAttributeMaxDynamicSharedMemorySize, GSMEM);
    cudaFuncSetAttribute(q_mma_kernel,
                         cudaFuncAttributeMaxDynamicSharedMemorySize, QSMEM);

    pack_in_kernel<<<(B_ROWS * 136 + 255) / 256, 256>>>(obs, act);
    conv_w_kernel<<<(EMB * KIN / 4 + 4 * HID * EMB / 4 + NQ * HID / 4 + 255) / 256, 256>>>(
        W1, Wih, W2);
    hvec_kernel<<<256, 256>>>(Whh, hst, bih, bhh);

    // x = relu(g_in @ g_w1^T + b1)
    mma_gemm_kernel<0><<<dim3(EMB / 256, B_ROWS / 128), 256, GSMEM>>>(b1, cst, out);
    // gates + LSTM cell
    mma_gemm_kernel<1><<<dim3(4 * HID / 256, B_ROWS / 128), 256, GSMEM>>>(b1, cst, out);
    // q
    q_mma_kernel<<<B_ROWS / 128, 128, QSMEM>>>(b2, out);
}

// round 14
// speedup vs baseline: 1.9181x; 1.0744x over previous
#include <cuda_runtime.h>
#include <cuda_fp16.h>
#include <cstdint>

// ---------------------------------------------------------------------------
// DRQN fused pipeline (sm_103 base ISA, legacy mma.sync fp16 — tcgen05 is
// compiler-gated off for this problem). R14 == R13 with the gemm2 launch-grid
// fix (grid.x = HID/64 = 8; R13's 4*HID/64 = 32 sent hb to 1984 -> OOB on
// g_wih/g_hvec reads and g_h writes -> illegal memory access).
//   * GEMM1 converts obs/act fp32->fp16 in its A-feed (no pack kernel).
//   * GEMM2: BK=64, 3-stage cp.async ring -> 8 barriers instead of 16.
// HMMA issue rate is the wall (~0.112 instr/cyc/SMSP, ~250-280 TF/s fp16).
//
// NOTE: __device__ globals are ONLY referenced from device code (GB300 ATS
// silently reads the host shadow if passed as host-side kernel args).
//
//   hvec = W_hh@h + b_ih + b_hh                  (fp32, exact)
//   x    = relu([obs|act] @ W1^T + b1)           GEMM1 BM128 BN256 fp16
//   gates= x @ Wih^T (gate-interleaved) -> LSTM  GEMM2 BM128 BN256 BK64 fp16
//   q    = h @ W2^T + b2                         GEMM3 BM128 BN32  fp16
// Output: [ q (B*32) | h_new[B-1] (512) | c_new[B-1] (512) ]
// ---------------------------------------------------------------------------

#define B_ROWS 32768
#define OBS    512
#define ACT    32
#define KIN    544
#define EMB    512
#define HID    512
#define NQ     32

__device__ __half g_x [(size_t)B_ROWS * EMB];
__device__ __half g_h [(size_t)B_ROWS * HID];
__device__ __half g_w1 [EMB * KIN];
__device__ __half g_wih[4 * HID * EMB];
__device__ __half g_w2 [NQ * HID];
__device__ float  g_hvec[4 * HID];

// ------------------------------ helpers -----------------------------------
__device__ __forceinline__ uint32_t smem_u32(const void* p) {
    uint32_t a;
    asm("{ .reg .u64 t; cvta.to.shared.u64 t, %1; cvt.u32.u64 %0, t; }"
        : "=r"(a) : "l"(p));
    return a;
}
__device__ __forceinline__ uint32_t h2u(float a, float b) {
    __half2 h = __floats2half2_rn(a, b);
    return *(uint32_t*)&h;
}
__device__ __forceinline__ uint2 r4h(float4 v) {      // 4 floats -> 4 halves
    return make_uint2(h2u(v.x, v.y), h2u(v.z, v.w));
}
__device__ __forceinline__ void ldsm4(uint32_t* r, uint32_t addr) {
    asm volatile("ldmatrix.sync.aligned.m8n8.x4.shared.b16 {%0,%1,%2,%3}, [%4];"
                 : "=r"(r[0]), "=r"(r[1]), "=r"(r[2]), "=r"(r[3]) : "r"(addr));
}
__device__ __forceinline__ void mma_h(float* c, const uint32_t* a,
                                      uint32_t b0, uint32_t b1) {
    asm volatile(
        "mma.sync.aligned.m16n8k16.row.col.f32.f16.f16.f32 "
        "{%0,%1,%2,%3}, {%4,%5,%6,%7}, {%8,%9}, {%0,%1,%2,%3};"
        : "+f"(c[0]), "+f"(c[1]), "+f"(c[2]), "+f"(c[3])
        : "r"(a[0]), "r"(a[1]), "r"(a[2]), "r"(a[3]), "r"(b0), "r"(b1));
}
#define CP16(dst, src) asm volatile("cp.async.cg.shared.global [%0], [%1], 16;" :: "r"(dst), "l"(src) : "memory")
#define CP_COMMIT()    asm volatile("cp.async.commit_group;" ::: "memory")
#define CP_WAIT2()     asm volatile("cp.async.wait_group 2;" ::: "memory")
#define CP_WAIT1()     asm volatile("cp.async.wait_group 1;" ::: "memory")

__device__ __forceinline__ float sigmoidf_(float x) {
    return __fdividef(1.f, 1.f + __expf(-x));
}
__device__ __forceinline__ float tanhf_(float x) {
    return __fdividef(2.f, 1.f + __expf(-2.f * x)) - 1.f;
}

// ---------------------------------------------------------------------------
// Pre-pass: fp16 weight copies (input pack is fused into GEMM1 now).
// ---------------------------------------------------------------------------
__global__ void __launch_bounds__(256) conv_w_kernel(
    const float* __restrict__ W1, const float* __restrict__ Wih,
    const float* __restrict__ W2)
{
    int id = blockIdx.x * 256 + threadIdx.x;           // float4 index
    const int N1 = EMB * KIN / 4, N2 = N1 + 4 * HID * EMB / 4;
    const int N3 = N2 + NQ * HID / 4;
    if (id < N1)      *(uint2*)(g_w1  + 4 * id)        = r4h(*(const float4*)(W1  + 4 * id));
    else if (id < N2) *(uint2*)(g_wih + 4 * (id - N1)) = r4h(*(const float4*)(Wih + 4 * (size_t)(id - N1)));
    else if (id < N3) *(uint2*)(g_w2  + 4 * (id - N2)) = r4h(*(const float4*)(W2  + 4 * (id - N2)));
}

// ---------------------------------------------------------------------------
// K0: hvec[n] = dot(W_hh[n,:], h) + b_ih[n] + b_hh[n]   (exact fp32)
// ---------------------------------------------------------------------------
__global__ void __launch_bounds__(256) hvec_kernel(
    const float* __restrict__ Whh, const float* __restrict__ h,
    const float* __restrict__ bih, const float* __restrict__ bhh)
{
    int w    = (blockIdx.x * blockDim.x + threadIdx.x) >> 5;
    int lane = threadIdx.x & 31;
    if (w >= 4 * HID) return;
    const float* row = Whh + (size_t)w * HID;
    float s = 0.f;
    #pragma unroll
    for (int k = 0; k < HID; k += 32) s += row[k + lane] * h[k + lane];
    #pragma unroll
    for (int o = 16; o > 0; o >>= 1) s += __shfl_xor_sync(0xffffffffu, s, o);
    if (lane == 0) g_hvec[w] = s + bih[w] + bhh[w];
}

// ---------------------------------------------------------------------------
// GEMM1: x = relu([obs|act] @ W1^T + b1). BM=128 BN=256 BK=32, 8 warps
// (64x64), 4 stages. A: LDG fp32 + cvt + STS (reg-prefetch, fuses the input
// pack); B: cp.async from g_w1.
// ---------------------------------------------------------------------------
#define NS1 4
#define STG1 24576
#define GSMEM1 (2048 + NS1 * STG1)     // 100352

__global__ void __launch_bounds__(256, 1) gemm1_kernel(
    const float* __restrict__ obs, const float* __restrict__ act,
    const float* __restrict__ b1)
{
    constexpr int KT = KIN / 32;                       // 17
    extern __shared__ char smem[];
    float* s_aux = (float*)smem;
    char*  tiles = smem + 2048;
    const uint32_t tiles_u = smem_u32(tiles);

    const int tid = threadIdx.x, lane = tid & 31, wid = tid >> 5;
    const int m0w = 64 * (wid & 1), n0w = 64 * (wid >> 1);
    const int rowBase = blockIdx.y * 128;
    const int colBase = blockIdx.x * 256;

    s_aux[tid] = b1[colBase + tid];

    // A-feed: 2 chunks/thread (16B fp16 = 8 halves); fp32 sources.
    const float* obs_row[2]; const float* act_row[2];
    int ck[2]; uint32_t aoff[2];
    #pragma unroll
    for (int j = 0; j < 2; j++) {
        int m = (tid + 256 * j) >> 2, c = tid & 3;
        obs_row[j] = obs + (size_t)(rowBase + m) * OBS;
        act_row[j] = act + (size_t)(rowBase + m) * ACT;
        ck[j] = 8 * c;
        aoff[j] = m * 64 + ((c ^ (m & 3)) << 4);
    }
    // B-feed: 4 chunks/thread via cp.async.
    const char* bptr[4]; uint32_t boff[4];
    #pragma unroll
    for (int j = 0; j < 4; j++) {
        int id = tid + 256 * j;
        int r = id >> 2, c = id & 3;
        bptr[j] = (const char*)(g_w1 + (size_t)(colBase + r) * KIN + 8 * c);
        boff[j] = 8192 + r * 64 + ((c ^ (r & 3)) << 4);
    }

    const int a_m  = m0w + (lane & 15);
    const int a_cb = lane >> 4, a_sw = a_m & 3;
    const int b_n  = n0w + (lane & 7) + ((lane & 16) >> 1);
    const int b_cb = (lane >> 3) & 1, b_sw = b_n & 3;

    float acc[4][8][4];
    #pragma unroll
    for (int i = 0; i < 4; i++)
        #pragma unroll
        for (int j = 0; j < 8; j++)
            #pragma unroll
            for (int k = 0; k < 4; k++) acc[i][j][k] = 0.f;

    float4 av[2][2];
    auto aLdg = [&](int t) {
        #pragma unroll
        for (int j = 0; j < 2; j++) {
            int kk = t * 32 + ck[j];
            const float* p = (kk < OBS) ? obs_row[j] + kk : act_row[j] + (kk - OBS);
            av[j][0] = *(const float4*)p;
            av[j][1] = *(const float4*)(p + 4);
        }
    };
    auto aSts = [&](int t) {
        #pragma unroll
        for (int j = 0; j < 2; j++) {
            uint2 u0 = r4h(av[j][0]), u1 = r4h(av[j][1]);
            *(uint4*)(tiles + (t & (NS1 - 1)) * STG1 + aoff[j]) =
                make_uint4(u0.x, u0.y, u1.x, u1.y);
        }
    };
    auto issueB = [&](int t) {
        uint32_t base = tiles_u + (t & (NS1 - 1)) * STG1;
        size_t ko = (size_t)t * 64;
        #pragma unroll
        for (int j = 0; j < 4; j++) CP16(base + boff[j], bptr[j] + ko);
        CP_COMMIT();
    };
    auto compute = [&](int s) {
        const uint32_t Ab = tiles_u + s * STG1, Bb = Ab + 8192;
        #pragma unroll
        for (int ks = 0; ks < 2; ks++) {
            uint32_t af[4][4], bf[4][4];
            #pragma unroll
            for (int mi = 0; mi < 4; mi++)
                ldsm4(af[mi], Ab + (a_m + 16 * mi) * 64 + (((2 * ks + a_cb) ^ a_sw) << 4));
            #pragma unroll
            for (int p = 0; p < 4; p++)
                ldsm4(bf[p], Bb + (b_n + 16 * p) * 64 + (((2 * ks + b_cb) ^ b_sw) << 4));
            #pragma unroll
            for (int mi = 0; mi < 4; mi++)
                #pragma unroll
                for (int ni = 0; ni < 8; ni++)
                    mma_h(acc[mi][ni], af[mi],
                          bf[ni >> 1][(ni & 1) * 2], bf[ni >> 1][(ni & 1) * 2 + 1]);
        }
    };

    aLdg(0); aSts(0); issueB(0);
    aLdg(1); aSts(1); issueB(1);
    aLdg(2); aSts(2); issueB(2);
    for (int t = 0; t < KT; t++) {
        CP_WAIT2();
        __syncthreads();
        if (t + 3 < KT) aLdg(t + 3);
        compute(t & (NS1 - 1));
        if (t + 3 < KT) { aSts(t + 3); issueB(t + 3); } else CP_COMMIT();
    }

    #pragma unroll
    for (int mi = 0; mi < 4; mi++) {
        int r = rowBase + m0w + 16 * mi + (lane >> 2);
        #pragma unroll
        for (int ni = 0; ni < 8; ni++) {
            int cl = n0w + 8 * ni + 2 * (lane & 3);
            __half* d0 = g_x + (size_t)r * EMB + colBase + cl;
            *(uint32_t*)d0 = h2u(fmaxf(acc[mi][ni][0] + s_aux[cl], 0.f),
                                 fmaxf(acc[mi][ni][1] + s_aux[cl + 1], 0.f));
            *(uint32_t*)(d0 + 8 * EMB) =
                         h2u(fmaxf(acc[mi][ni][2] + s_aux[cl], 0.f),
                             fmaxf(acc[mi][ni][3] + s_aux[cl + 1], 0.f));
        }
    }
}

// ---------------------------------------------------------------------------
// GEMM2: gate-interleaved gates GEMM + LSTM cell. BM=128 BN=256 BK=64,
// 8 warps (64x64), 3-stage cp.async ring (8 barriers total).
// Stage layout: A0(8K) A1(8K) B0(16K) B1(16K) = 48K. grid (HID/64=8, 256).
// ---------------------------------------------------------------------------
#define STG2 49152
#define GSMEM2 (2048 + 3 * STG2)       // 149504

__global__ void __launch_bounds__(256, 1) gemm2_kernel(
    const float* __restrict__ cell, float* __restrict__ out)
{
    constexpr int KT = EMB / 64;                       // 8
    extern __shared__ char smem[];
    float* s_aux = (float*)smem;
    char*  tiles = smem + 2048;
    float* s_epi = (float*)tiles;
    const uint32_t tiles_u = smem_u32(tiles);

    const int tid = threadIdx.x, lane = tid & 31, wid = tid >> 5;
    const int m0w = 64 * (wid & 1), n0w = 64 * (wid >> 1);
    const int rowBase = blockIdx.y * 128;
    const int hb      = blockIdx.x * 64;               // hid base, 0..448

    if (tid < 64) s_aux[tid] = cell[hb + tid];
    s_aux[64 + tid] = g_hvec[((tid >> 6) << 9) + hb + (tid & 63)];

    const char* aptr[2]; uint32_t aoff[2];
    #pragma unroll
    for (int j = 0; j < 2; j++) {
        int m = (tid + 256 * j) >> 2, c = tid & 3;
        aptr[j] = (const char*)(g_x + (size_t)(rowBase + m) * EMB + 8 * c);
        aoff[j] = m * 64 + ((c ^ (m & 3)) << 4);
    }
    const char* bptr[4]; uint32_t boff[4];
    #pragma unroll
    for (int j = 0; j < 4; j++) {
        int id = tid + 256 * j;
        int r = id >> 2, c = id & 3;
        int wr = ((r & 3) << 9) + hb + (r >> 2);       // 512*gate + hid
        bptr[j] = (const char*)(g_wih + (size_t)wr * EMB + 8 * c);
        boff[j] = r * 64 + ((c ^ (r & 3)) << 4);
    }

    const int a_m  = m0w + (lane & 15);
    const int a_cb = lane >> 4, a_sw = a_m & 3;
    const int b_n  = n0w + (lane & 7) + ((lane & 16) >> 1);
    const int b_cb = (lane >> 3) & 1, b_sw = b_n & 3;

    float acc[4][8][4];
    #pragma unroll
    for (int i = 0; i < 4; i++)
        #pragma unroll
        for (int j = 0; j < 8; j++)
            #pragma unroll
            for (int k = 0; k < 4; k++) acc[i][j][k] = 0.f;

    auto issue = [&](int t, int st) {
        uint32_t base = tiles_u + st * STG2;
        #pragma unroll
        for (int u = 0; u < 2; u++) {
            size_t ko = (size_t)t * 128 + u * 64;
            #pragma unroll
            for (int j = 0; j < 2; j++)
                CP16(base + u * 8192 + aoff[j], aptr[j] + ko);
            #pragma unroll
            for (int j = 0; j < 4; j++)
                CP16(base + 16384 + u * 16384 + boff[j], bptr[j] + ko);
        }
        CP_COMMIT();
    };
    auto compute = [&](int s) {
        #pragma unroll
        for (int u = 0; u < 2; u++) {
            const uint32_t Ab = tiles_u + s * STG2 + u * 8192;
            const uint32_t Bb = tiles_u + s * STG2 + 16384 + u * 16384;
            #pragma unroll
            for (int ks = 0; ks < 2; ks++) {
                uint32_t af[4][4], bf[4][4];
                #pragma unroll
                for (int mi = 0; mi < 4; mi++)
                    ldsm4(af[mi], Ab + (a_m + 16 * mi) * 64 + (((2 * ks + a_cb) ^ a_sw) << 4));
                #pragma unroll
                for (int p = 0; p < 4; p++)
                    ldsm4(bf[p], Bb + (b_n + 16 * p) * 64 + (((2 * ks + b_cb) ^ b_sw) << 4));
                #pragma unroll
                for (int mi = 0; mi < 4; mi++)
                    #pragma unroll
                    for (int ni = 0; ni < 8; ni++)
                        mma_h(acc[mi][ni], af[mi],
                              bf[ni >> 1][(ni & 1) * 2], bf[ni >> 1][(ni & 1) * 2 + 1]);
            }
        }
    };

    issue(0, 0); issue(1, 1);
    int cs_ = 0, is_ = 2;
    for (int t = 0; t < KT; t++) {
        CP_WAIT1();
        __syncthreads();
        compute(cs_);
        cs_ = (cs_ == 2) ? 0 : cs_ + 1;
        if (t + 2 < KT) {
            issue(t + 2, is_);
            is_ = (is_ == 2) ? 0 : is_ + 1;
        } else CP_COMMIT();
    }

    // ---- LSTM epilogue (gate shuffle + smem-staged coalesced g_h store) ----
    __syncthreads();
    #pragma unroll
    for (int mi = 0; mi < 4; mi++) {
        #pragma unroll
        for (int ni = 0; ni < 8; ni++) {
            float c0 = acc[mi][ni][0], c1 = acc[mi][ni][1];
            float c2 = acc[mi][ni][2], c3 = acc[mi][ni][3];
            float e0 = __shfl_xor_sync(0xffffffffu, c0, 1);
            float e1 = __shfl_xor_sync(0xffffffffu, c1, 1);
            float e2 = __shfl_xor_sync(0xffffffffu, c2, 1);
            float e3 = __shfl_xor_sync(0xffffffffu, c3, 1);
            bool ev = !(lane & 1);
            int rl = m0w + 16 * mi + (lane >> 2) + (ev ? 0 : 8);
            float gi = ev ? c0 : e2;
            float gf = ev ? c1 : e3;
            float gg = ev ? e0 : c2;
            float go = ev ? e1 : c3;
            int hl = (n0w >> 2) + 2 * ni + ((lane & 3) >> 1);
            float iv = sigmoidf_(gi + s_aux[64 + hl]);
            float fv = sigmoidf_(gf + s_aux[128 + hl]);
            float gv = tanhf_   (gg + s_aux[192 + hl]);
            float ov = sigmoidf_(go + s_aux[256 + hl]);
            float cn = fv * s_aux[hl] + iv * gv;
            float hn = ov * tanhf_(cn);
            s_epi[rl * 68 + hl] = hn;
            if (rowBase + rl == B_ROWS - 1) {
                out[(size_t)B_ROWS * NQ + hb + hl]       = hn;
                out[(size_t)B_ROWS * NQ + HID + hb + hl] = cn;
            }
        }
    }
    __syncthreads();
    #pragma unroll
    for (int i = 0; i < 8; i++) {
        int id = tid + 256 * i;
        int r = id >> 4, c4 = (id & 15) * 4;
        float4 v = *(float4*)&s_epi[r * 68 + c4];
        *(uint2*)(g_h + (size_t)(rowBase + r) * HID + hb + c4) = r4h(v);
    }
}

// ---------------------------------------------------------------------------
// GEMM3: q = g_h @ g_w2^T + b2. BM=128, BN=32, 128 thr (4 warps, 64x16), 4 st.
// ---------------------------------------------------------------------------
#define QSTG 10240
#define QSMEM (4 * QSTG)               // 40960

__global__ void __launch_bounds__(128) q_mma_kernel(
    const float* __restrict__ b2, float* __restrict__ q)
{
    extern __shared__ char smem[];
    const uint32_t tiles_u = smem_u32(smem);
    const int tid = threadIdx.x, lane = tid & 31, wid = tid >> 5;
    const int m0w = 64 * (wid & 1), n0w = 16 * (wid >> 1);
    const int rowBase = blockIdx.x * 128;

    const char* aptr[4]; uint32_t aoff[4];
    #pragma unroll
    for (int j = 0; j < 4; j++) {
        int m = (tid + 128 * j) >> 2, c = tid & 3;
        aptr[j] = (const char*)(g_h + (size_t)(rowBase + m) * HID + 8 * c);
        aoff[j] = m * 64 + ((c ^ (m & 3)) << 4);
    }
    const int br = tid >> 2, bc = tid & 3;
    const char* bptr = (const char*)(g_w2 + (size_t)br * HID + 8 * bc);
    const uint32_t boff = 8192 + br * 64 + ((bc ^ (br & 3)) << 4);

    const int a_m  = m0w + (lane & 15);
    const int a_cb = lane >> 4, a_sw = a_m & 3;
    const int b_n  = n0w + (lane & 7) + ((lane & 16) >> 1);
    const int b_cb = (lane >> 3) & 1, b_sw = b_n & 3;

    float acc[4][2][4];
    #pragma unroll
    for (int i = 0; i < 4; i++)
        #pragma unroll
        for (int j = 0; j < 2; j++)
            #pragma unroll
            for (int k = 0; k < 4; k++) acc[i][j][k] = 0.f;

    auto issue = [&](int t) {
        uint32_t base = tiles_u + (t & 3) * QSTG;
        size_t ko = (size_t)t * 64;
        #pragma unroll
        for (int j = 0; j < 4; j++) CP16(base + aoff[j], aptr[j] + ko);
        CP16(base + boff, bptr + ko);
        CP_COMMIT();
    };

    issue(0); issue(1); issue(2);
    const int KT = HID / 32;
    for (int t = 0; t < KT; t++) {
        CP_WAIT2();
        __syncthreads();
        const uint32_t Ab = tiles_u + (t & 3) * QSTG, Bb = Ab + 8192;
        #pragma unroll
        for (int ks = 0; ks < 2; ks++) {
            uint32_t af[4][4], bf[4];
            #pragma unroll
            for (int mi = 0; mi < 4; mi++)
                ldsm4(af[mi], Ab + (a_m + 16 * mi) * 64 + (((2 * ks + a_cb) ^ a_sw) << 4));
            ldsm4(bf, Bb + b_n * 64 + (((2 * ks + b_cb) ^ b_sw) << 4));
            #pragma unroll
            for (int mi = 0; mi < 4; mi++)
                #pragma unroll
                for (int ni = 0; ni < 2; ni++)
                    mma_h(acc[mi][ni], af[mi], bf[ni * 2], bf[ni * 2 + 1]);
        }
        if (t + 3 < KT) issue(t + 3); else CP_COMMIT();
    }

    #pragma unroll
    for (int mi = 0; mi < 4; mi++) {
        int r = rowBase + m0w + 16 * mi + (lane >> 2);
        #pragma unroll
        for (int ni = 0; ni < 2; ni++) {
            int cl = n0w + 8 * ni + 2 * (lane & 3);
            float bb0 = __ldg(b2 + cl), bb1 = __ldg(b2 + cl + 1);
            float* d0 = q + (size_t)r * NQ + cl;
            *(float2*)d0 = make_float2(acc[mi][ni][0] + bb0, acc[mi][ni][1] + bb1);
            *(float2*)(d0 + 8 * NQ) = make_float2(acc[mi][ni][2] + bb0, acc[mi][ni][3] + bb1);
        }
    }
}

// ---------------------------------------------------------------------------
extern "C" void kernel_launch(void* const* d_in, const int* in_sizes, int n_in,
                              void* d_out, int out_size)
{
    const float* obs = (const float*)d_in[0];
    const float* act = (const float*)d_in[1];
    const float* hst = (const float*)d_in[2];
    const float* cst = (const float*)d_in[3];
    const float* W1  = (const float*)d_in[4];
    const float* b1  = (const float*)d_in[5];
    const float* Wih = (const float*)d_in[6];
    const float* bih = (const float*)d_in[7];
    const float* Whh = (const float*)d_in[8];
    const float* bhh = (const float*)d_in[9];
    const float* W2  = (const float*)d_in[10];
    const float* b2  = (const float*)d_in[11];
    float* out = (float*)d_out;

    cudaFuncSetAttribute(gemm1_kernel,
                         cudaFuncAttributeMaxDynamicSharedMemorySize, GSMEM1);
    cudaFuncSetAttribute(gemm2_kernel,
                         cudaFuncAttributeMaxDynamicSharedMemorySize, GSMEM2);
    cudaFuncSetAttribute(q_mma_kernel,
                         cudaFuncAttributeMaxDynamicSharedMemorySize, QSMEM);

    conv_w_kernel<<<(EMB * KIN / 4 + 4 * HID * EMB / 4 + NQ * HID / 4 + 255) / 256, 256>>>(
        W1, Wih, W2);
    hvec_kernel<<<256, 256>>>(Whh, hst, bih, bhh);

    gemm1_kernel<<<dim3(EMB / 256, B_ROWS / 128), 256, GSMEM1>>>(obs, act, b1);
    // FIX: BN=256 covers 64 hid columns -> grid.x = HID/64 = 8 (was 32 in R13)
    gemm2_kernel<<<dim3(HID / 64, B_ROWS / 128), 256, GSMEM2>>>(cst, out);
    q_mma_kernel<<<B_ROWS / 128, 128, QSMEM>>>(b2, out);
}

// round 16
// speedup vs baseline: 1.9481x; 1.0156x over previous
#include <cuda_runtime.h>
#include <cuda_fp16.h>
#include <cstdint>

// ---------------------------------------------------------------------------
// DRQN fused pipeline (sm_103 base ISA, legacy mma.sync fp16 — tcgen05 is
// compiler-gated off for this problem). R16 == R15 with the gemm1-tail chunk
// count fixed: W_ih is 1,048,576 floats = 262,144 float4 chunks (R15 used
// 524,288 -> 2x OOB on Wih reads and g_wih writes -> illegal access).
// Each of 512 CTAs converts 512 chunks (2/thread).
//
//   * prep_kernel: W1/W2 fp16 copies + hvec in one launch.
//   * gemm1 TAIL converts W_ih (rides idle LSU under the HMMA rate cap).
//   * GEMM mainloops unchanged from R14 (all at the ~rt15 HMMA issue floor).
//
// NOTE: __device__ globals are ONLY referenced from device code (GB300 ATS
// silently reads the host shadow if passed as host-side kernel args).
//
//   hvec = W_hh@h + b_ih + b_hh                  (fp32, exact)
//   x    = relu([obs|act] @ W1^T + b1)           GEMM1 BM128 BN256 fp16
//   gates= x @ Wih^T (gate-interleaved) -> LSTM  GEMM2 BM128 BN256 BK64 fp16
//   q    = h @ W2^T + b2                         GEMM3 BM128 BN32  fp16
// Output: [ q (B*32) | h_new[B-1] (512) | c_new[B-1] (512) ]
// ---------------------------------------------------------------------------

#define B_ROWS 32768
#define OBS    512
#define ACT    32
#define KIN    544
#define EMB    512
#define HID    512
#define NQ     32

__device__ __half g_x [(size_t)B_ROWS * EMB];
__device__ __half g_h [(size_t)B_ROWS * HID];
__device__ __half g_w1 [EMB * KIN];
__device__ __half g_wih[4 * HID * EMB];
__device__ __half g_w2 [NQ * HID];
__device__ float  g_hvec[4 * HID];

// ------------------------------ helpers -----------------------------------
__device__ __forceinline__ uint32_t smem_u32(const void* p) {
    uint32_t a;
    asm("{ .reg .u64 t; cvta.to.shared.u64 t, %1; cvt.u32.u64 %0, t; }"
        : "=r"(a) : "l"(p));
    return a;
}
__device__ __forceinline__ uint32_t h2u(float a, float b) {
    __half2 h = __floats2half2_rn(a, b);
    return *(uint32_t*)&h;
}
__device__ __forceinline__ uint2 r4h(float4 v) {      // 4 floats -> 4 halves
    return make_uint2(h2u(v.x, v.y), h2u(v.z, v.w));
}
__device__ __forceinline__ void ldsm4(uint32_t* r, uint32_t addr) {
    asm volatile("ldmatrix.sync.aligned.m8n8.x4.shared.b16 {%0,%1,%2,%3}, [%4];"
                 : "=r"(r[0]), "=r"(r[1]), "=r"(r[2]), "=r"(r[3]) : "r"(addr));
}
__device__ __forceinline__ void mma_h(float* c, const uint32_t* a,
                                      uint32_t b0, uint32_t b1) {
    asm volatile(
        "mma.sync.aligned.m16n8k16.row.col.f32.f16.f16.f32 "
        "{%0,%1,%2,%3}, {%4,%5,%6,%7}, {%8,%9}, {%0,%1,%2,%3};"
        : "+f"(c[0]), "+f"(c[1]), "+f"(c[2]), "+f"(c[3])
        : "r"(a[0]), "r"(a[1]), "r"(a[2]), "r"(a[3]), "r"(b0), "r"(b1));
}
#define CP16(dst, src) asm volatile("cp.async.cg.shared.global [%0], [%1], 16;" :: "r"(dst), "l"(src) : "memory")
#define CP_COMMIT()    asm volatile("cp.async.commit_group;" ::: "memory")
#define CP_WAIT2()     asm volatile("cp.async.wait_group 2;" ::: "memory")
#define CP_WAIT1()     asm volatile("cp.async.wait_group 1;" ::: "memory")

__device__ __forceinline__ float sigmoidf_(float x) {
    return __fdividef(1.f, 1.f + __expf(-x));
}
__device__ __forceinline__ float tanhf_(float x) {
    return __fdividef(2.f, 1.f + __expf(-2.f * x)) - 1.f;
}

// ---------------------------------------------------------------------------
// prep_kernel: W1 + W2 fp16 copies, and hvec = W_hh@h + b_ih + b_hh.
// Blocks [0, NCONV): weight conversion. Blocks [NCONV, NCONV+256): hvec.
// ---------------------------------------------------------------------------
#define NW1C (EMB * KIN / 4)           // 69632 float4 chunks
#define NW2C (NQ * HID / 4)            // 4096
#define NCONV ((NW1C + NW2C + 255) / 256)   // 288 blocks

__global__ void __launch_bounds__(256) prep_kernel(
    const float* __restrict__ W1, const float* __restrict__ W2,
    const float* __restrict__ Whh, const float* __restrict__ h,
    const float* __restrict__ bih, const float* __restrict__ bhh)
{
    if (blockIdx.x < NCONV) {
        int id = blockIdx.x * 256 + threadIdx.x;
        if (id < NW1C)
            *(uint2*)(g_w1 + 4 * id) = r4h(*(const float4*)(W1 + 4 * id));
        else if (id < NW1C + NW2C)
            *(uint2*)(g_w2 + 4 * (id - NW1C)) =
                r4h(*(const float4*)(W2 + 4 * (id - NW1C)));
        return;
    }
    int w    = ((blockIdx.x - NCONV) * 256 + threadIdx.x) >> 5;   // 0..2047
    int lane = threadIdx.x & 31;
    const float* row = Whh + (size_t)w * HID;
    float s = 0.f;
    #pragma unroll
    for (int k = 0; k < HID; k += 32) s += row[k + lane] * h[k + lane];
    #pragma unroll
    for (int o = 16; o > 0; o >>= 1) s += __shfl_xor_sync(0xffffffffu, s, o);
    if (lane == 0) g_hvec[w] = s + bih[w] + bhh[w];
}

// ---------------------------------------------------------------------------
// GEMM1: x = relu([obs|act] @ W1^T + b1). BM=128 BN=256 BK=32, 8 warps
// (64x64), 4 stages. A: LDG fp32 + cvt + STS; B: cp.async from g_w1.
// TAIL: each CTA converts 1/512 of W_ih -> g_wih (512 chunks = 2/thread).
// ---------------------------------------------------------------------------
#define NS1 4
#define STG1 24576
#define GSMEM1 (2048 + NS1 * STG1)     // 100352

__global__ void __launch_bounds__(256, 1) gemm1_kernel(
    const float* __restrict__ obs, const float* __restrict__ act,
    const float* __restrict__ b1,  const float* __restrict__ Wih)
{
    constexpr int KT = KIN / 32;                       // 17
    extern __shared__ char smem[];
    float* s_aux = (float*)smem;
    char*  tiles = smem + 2048;
    const uint32_t tiles_u = smem_u32(tiles);

    const int tid = threadIdx.x, lane = tid & 31, wid = tid >> 5;
    const int m0w = 64 * (wid & 1), n0w = 64 * (wid >> 1);
    const int rowBase = blockIdx.y * 128;
    const int colBase = blockIdx.x * 256;

    s_aux[tid] = b1[colBase + tid];

    // A-feed: 2 chunks/thread (16B fp16 = 8 halves); fp32 sources.
    const float* obs_row[2]; const float* act_row[2];
    int ck[2]; uint32_t aoff[2];
    #pragma unroll
    for (int j = 0; j < 2; j++) {
        int m = (tid + 256 * j) >> 2, c = tid & 3;
        obs_row[j] = obs + (size_t)(rowBase + m) * OBS;
        act_row[j] = act + (size_t)(rowBase + m) * ACT;
        ck[j] = 8 * c;
        aoff[j] = m * 64 + ((c ^ (m & 3)) << 4);
    }
    // B-feed: 4 chunks/thread via cp.async.
    const char* bptr[4]; uint32_t boff[4];
    #pragma unroll
    for (int j = 0; j < 4; j++) {
        int id = tid + 256 * j;
        int r = id >> 2, c = id & 3;
        bptr[j] = (const char*)(g_w1 + (size_t)(colBase + r) * KIN + 8 * c);
        boff[j] = 8192 + r * 64 + ((c ^ (r & 3)) << 4);
    }

    const int a_m  = m0w + (lane & 15);
    const int a_cb = lane >> 4, a_sw = a_m & 3;
    const int b_n  = n0w + (lane & 7) + ((lane & 16) >> 1);
    const int b_cb = (lane >> 3) & 1, b_sw = b_n & 3;

    float acc[4][8][4];
    #pragma unroll
    for (int i = 0; i < 4; i++)
        #pragma unroll
        for (int j = 0; j < 8; j++)
            #pragma unroll
            for (int k = 0; k < 4; k++) acc[i][j][k] = 0.f;

    float4 av[2][2];
    auto aLdg = [&](int t) {
        #pragma unroll
        for (int j = 0; j < 2; j++) {
            int kk = t * 32 + ck[j];
            const float* p = (kk < OBS) ? obs_row[j] + kk : act_row[j] + (kk - OBS);
            av[j][0] = *(const float4*)p;
            av[j][1] = *(const float4*)(p + 4);
        }
    };
    auto aSts = [&](int t) {
        #pragma unroll
        for (int j = 0; j < 2; j++) {
            uint2 u0 = r4h(av[j][0]), u1 = r4h(av[j][1]);
            *(uint4*)(tiles + (t & (NS1 - 1)) * STG1 + aoff[j]) =
                make_uint4(u0.x, u0.y, u1.x, u1.y);
        }
    };
    auto issueB = [&](int t) {
        uint32_t base = tiles_u + (t & (NS1 - 1)) * STG1;
        size_t ko = (size_t)t * 64;
        #pragma unroll
        for (int j = 0; j < 4; j++) CP16(base + boff[j], bptr[j] + ko);
        CP_COMMIT();
    };
    auto compute = [&](int s) {
        const uint32_t Ab = tiles_u + s * STG1, Bb = Ab + 8192;
        #pragma unroll
        for (int ks = 0; ks < 2; ks++) {
            uint32_t af[4][4], bf[4][4];
            #pragma unroll
            for (int mi = 0; mi < 4; mi++)
                ldsm4(af[mi], Ab + (a_m + 16 * mi) * 64 + (((2 * ks + a_cb) ^ a_sw) << 4));
            #pragma unroll
            for (int p = 0; p < 4; p++)
                ldsm4(bf[p], Bb + (b_n + 16 * p) * 64 + (((2 * ks + b_cb) ^ b_sw) << 4));
            #pragma unroll
            for (int mi = 0; mi < 4; mi++)
                #pragma unroll
                for (int ni = 0; ni < 8; ni++)
                    mma_h(acc[mi][ni], af[mi],
                          bf[ni >> 1][(ni & 1) * 2], bf[ni >> 1][(ni & 1) * 2 + 1]);
        }
    };

    aLdg(0); aSts(0); issueB(0);
    aLdg(1); aSts(1); issueB(1);
    aLdg(2); aSts(2); issueB(2);
    for (int t = 0; t < KT; t++) {
        CP_WAIT2();
        __syncthreads();
        if (t + 3 < KT) aLdg(t + 3);
        compute(t & (NS1 - 1));
        if (t + 3 < KT) { aSts(t + 3); issueB(t + 3); } else CP_COMMIT();
    }

    #pragma unroll
    for (int mi = 0; mi < 4; mi++) {
        int r = rowBase + m0w + 16 * mi + (lane >> 2);
        #pragma unroll
        for (int ni = 0; ni < 8; ni++) {
            int cl = n0w + 8 * ni + 2 * (lane & 3);
            __half* d0 = g_x + (size_t)r * EMB + colBase + cl;
            *(uint32_t*)d0 = h2u(fmaxf(acc[mi][ni][0] + s_aux[cl], 0.f),
                                 fmaxf(acc[mi][ni][1] + s_aux[cl + 1], 0.f));
            *(uint32_t*)(d0 + 8 * EMB) =
                         h2u(fmaxf(acc[mi][ni][2] + s_aux[cl], 0.f),
                             fmaxf(acc[mi][ni][3] + s_aux[cl + 1], 0.f));
        }
    }

    // ---- TAIL: fused W_ih fp32->fp16 conversion ----
    // W_ih = 4*HID*EMB = 1,048,576 floats = 262,144 float4 chunks.
    // 512 CTAs x 512 chunks (256 thr x 2 chunks each).
    {
        const int cta = blockIdx.y * gridDim.x + blockIdx.x;   // 0..511
        #pragma unroll
        for (int j = 0; j < 2; j++) {
            size_t id4 = (size_t)cta * 512 + tid + 256 * j;    // < 262144
            *(uint2*)(g_wih + 4 * id4) = r4h(*(const float4*)(Wih + 4 * id4));
        }
    }
}

// ---------------------------------------------------------------------------
// GEMM2: gate-interleaved gates GEMM + LSTM cell. BM=128 BN=256 BK=64,
// 8 warps (64x64), 3-stage cp.async ring. grid (HID/64=8, 256).
// ---------------------------------------------------------------------------
#define STG2 49152
#define GSMEM2 (2048 + 3 * STG2)       // 149504

__global__ void __launch_bounds__(256, 1) gemm2_kernel(
    const float* __restrict__ cell, float* __restrict__ out)
{
    constexpr int KT = EMB / 64;                       // 8
    extern __shared__ char smem[];
    float* s_aux = (float*)smem;
    char*  tiles = smem + 2048;
    float* s_epi = (float*)tiles;
    const uint32_t tiles_u = smem_u32(tiles);

    const int tid = threadIdx.x, lane = tid & 31, wid = tid >> 5;
    const int m0w = 64 * (wid & 1), n0w = 64 * (wid >> 1);
    const int rowBase = blockIdx.y * 128;
    const int hb      = blockIdx.x * 64;               // hid base, 0..448

    if (tid < 64) s_aux[tid] = cell[hb + tid];
    s_aux[64 + tid] = g_hvec[((tid >> 6) << 9) + hb + (tid & 63)];

    const char* aptr[2]; uint32_t aoff[2];
    #pragma unroll
    for (int j = 0; j < 2; j++) {
        int m = (tid + 256 * j) >> 2, c = tid & 3;
        aptr[j] = (const char*)(g_x + (size_t)(rowBase + m) * EMB + 8 * c);
        aoff[j] = m * 64 + ((c ^ (m & 3)) << 4);
    }
    const char* bptr[4]; uint32_t boff[4];
    #pragma unroll
    for (int j = 0; j < 4; j++) {
        int id = tid + 256 * j;
        int r = id >> 2, c = id & 3;
        int wr = ((r & 3) << 9) + hb + (r >> 2);       // 512*gate + hid
        bptr[j] = (const char*)(g_wih + (size_t)wr * EMB + 8 * c);
        boff[j] = r * 64 + ((c ^ (r & 3)) << 4);
    }

    const int a_m  = m0w + (lane & 15);
    const int a_cb = lane >> 4, a_sw = a_m & 3;
    const int b_n  = n0w + (lane & 7) + ((lane & 16) >> 1);
    const int b_cb = (lane >> 3) & 1, b_sw = b_n & 3;

    float acc[4][8][4];
    #pragma unroll
    for (int i = 0; i < 4; i++)
        #pragma unroll
        for (int j = 0; j < 8; j++)
            #pragma unroll
            for (int k = 0; k < 4; k++) acc[i][j][k] = 0.f;

    auto issue = [&](int t, int st) {
        uint32_t base = tiles_u + st * STG2;
        #pragma unroll
        for (int u = 0; u < 2; u++) {
            size_t ko = (size_t)t * 128 + u * 64;
            #pragma unroll
            for (int j = 0; j < 2; j++)
                CP16(base + u * 8192 + aoff[j], aptr[j] + ko);
            #pragma unroll
            for (int j = 0; j < 4; j++)
                CP16(base + 16384 + u * 16384 + boff[j], bptr[j] + ko);
        }
        CP_COMMIT();
    };
    auto compute = [&](int s) {
        #pragma unroll
        for (int u = 0; u < 2; u++) {
            const uint32_t Ab = tiles_u + s * STG2 + u * 8192;
            const uint32_t Bb = tiles_u + s * STG2 + 16384 + u * 16384;
            #pragma unroll
            for (int ks = 0; ks < 2; ks++) {
                uint32_t af[4][4], bf[4][4];
                #pragma unroll
                for (int mi = 0; mi < 4; mi++)
                    ldsm4(af[mi], Ab + (a_m + 16 * mi) * 64 + (((2 * ks + a_cb) ^ a_sw) << 4));
                #pragma unroll
                for (int p = 0; p < 4; p++)
                    ldsm4(bf[p], Bb + (b_n + 16 * p) * 64 + (((2 * ks + b_cb) ^ b_sw) << 4));
                #pragma unroll
                for (int mi = 0; mi < 4; mi++)
                    #pragma unroll
                    for (int ni = 0; ni < 8; ni++)
                        mma_h(acc[mi][ni], af[mi],
                              bf[ni >> 1][(ni & 1) * 2], bf[ni >> 1][(ni & 1) * 2 + 1]);
            }
        }
    };

    issue(0, 0); issue(1, 1);
    int cs_ = 0, is_ = 2;
    for (int t = 0; t < KT; t++) {
        CP_WAIT1();
        __syncthreads();
        compute(cs_);
        cs_ = (cs_ == 2) ? 0 : cs_ + 1;
        if (t + 2 < KT) {
            issue(t + 2, is_);
            is_ = (is_ == 2) ? 0 : is_ + 1;
        } else CP_COMMIT();
    }

    // ---- LSTM epilogue (gate shuffle + smem-staged coalesced g_h store) ----
    __syncthreads();
    #pragma unroll
    for (int mi = 0; mi < 4; mi++) {
        #pragma unroll
        for (int ni = 0; ni < 8; ni++) {
            float c0 = acc[mi][ni][0], c1 = acc[mi][ni][1];
            float c2 = acc[mi][ni][2], c3 = acc[mi][ni][3];
            float e0 = __shfl_xor_sync(0xffffffffu, c0, 1);
            float e1 = __shfl_xor_sync(0xffffffffu, c1, 1);
            float e2 = __shfl_xor_sync(0xffffffffu, c2, 1);
            float e3 = __shfl_xor_sync(0xffffffffu, c3, 1);
            bool ev = !(lane & 1);
            int rl = m0w + 16 * mi + (lane >> 2) + (ev ? 0 : 8);
            float gi = ev ? c0 : e2;
            float gf = ev ? c1 : e3;
            float gg = ev ? e0 : c2;
            float go = ev ? e1 : c3;
            int hl = (n0w >> 2) + 2 * ni + ((lane & 3) >> 1);
            float iv = sigmoidf_(gi + s_aux[64 + hl]);
            float fv = sigmoidf_(gf + s_aux[128 + hl]);
            float gv = tanhf_   (gg + s_aux[192 + hl]);
            float ov = sigmoidf_(go + s_aux[256 + hl]);
            float cn = fv * s_aux[hl] + iv * gv;
            float hn = ov * tanhf_(cn);
            s_epi[rl * 68 + hl] = hn;
            if (rowBase + rl == B_ROWS - 1) {
                out[(size_t)B_ROWS * NQ + hb + hl]       = hn;
                out[(size_t)B_ROWS * NQ + HID + hb + hl] = cn;
            }
        }
    }
    __syncthreads();
    #pragma unroll
    for (int i = 0; i < 8; i++) {
        int id = tid + 256 * i;
        int r = id >> 4, c4 = (id & 15) * 4;
        float4 v = *(float4*)&s_epi[r * 68 + c4];
        *(uint2*)(g_h + (size_t)(rowBase + r) * HID + hb + c4) = r4h(v);
    }
}

// ---------------------------------------------------------------------------
// GEMM3: q = g_h @ g_w2^T + b2. BM=128, BN=32, 128 thr (4 warps, 64x16), 4 st.
// ---------------------------------------------------------------------------
#define QSTG 10240
#define QSMEM (4 * QSTG)               // 40960

__global__ void __launch_bounds__(128) q_mma_kernel(
    const float* __restrict__ b2, float* __restrict__ q)
{
    extern __shared__ char smem[];
    const uint32_t tiles_u = smem_u32(smem);
    const int tid = threadIdx.x, lane = tid & 31, wid = tid >> 5;
    const int m0w = 64 * (wid & 1), n0w = 16 * (wid >> 1);
    const int rowBase = blockIdx.x * 128;

    const char* aptr[4]; uint32_t aoff[4];
    #pragma unroll
    for (int j = 0; j < 4; j++) {
        int m = (tid + 128 * j) >> 2, c = tid & 3;
        aptr[j] = (const char*)(g_h + (size_t)(rowBase + m) * HID + 8 * c);
        aoff[j] = m * 64 + ((c ^ (m & 3)) << 4);
    }
    const int br = tid >> 2, bc = tid & 3;
    const char* bptr = (const char*)(g_w2 + (size_t)br * HID + 8 * bc);
    const uint32_t boff = 8192 + br * 64 + ((bc ^ (br & 3)) << 4);

    const int a_m  = m0w + (lane & 15);
    const int a_cb = lane >> 4, a_sw = a_m & 3;
    const int b_n  = n0w + (lane & 7) + ((lane & 16) >> 1);
    const int b_cb = (lane >> 3) & 1, b_sw = b_n & 3;

    float acc[4][2][4];
    #pragma unroll
    for (int i = 0; i < 4; i++)
        #pragma unroll
        for (int j = 0; j < 2; j++)
            #pragma unroll
            for (int k = 0; k < 4; k++) acc[i][j][k] = 0.f;

    auto issue = [&](int t) {
        uint32_t base = tiles_u + (t & 3) * QSTG;
        size_t ko = (size_t)t * 64;
        #pragma unroll
        for (int j = 0; j < 4; j++) CP16(base + aoff[j], aptr[j] + ko);
        CP16(base + boff, bptr + ko);
        CP_COMMIT();
    };

    issue(0); issue(1); issue(2);
    const int KT = HID / 32;
    for (int t = 0; t < KT; t++) {
        CP_WAIT2();
        __syncthreads();
        const uint32_t Ab = tiles_u + (t & 3) * QSTG, Bb = Ab + 8192;
        #pragma unroll
        for (int ks = 0; ks < 2; ks++) {
            uint32_t af[4][4], bf[4];
            #pragma unroll
            for (int mi = 0; mi < 4; mi++)
                ldsm4(af[mi], Ab + (a_m + 16 * mi) * 64 + (((2 * ks + a_cb) ^ a_sw) << 4));
            ldsm4(bf, Bb + b_n * 64 + (((2 * ks + b_cb) ^ b_sw) << 4));
            #pragma unroll
            for (int mi = 0; mi < 4; mi++)
                #pragma unroll
                for (int ni = 0; ni < 2; ni++)
                    mma_h(acc[mi][ni], af[mi], bf[ni * 2], bf[ni * 2 + 1]);
        }
        if (t + 3 < KT) issue(t + 3); else CP_COMMIT();
    }

    #pragma unroll
    for (int mi = 0; mi < 4; mi++) {
        int r = rowBase + m0w + 16 * mi + (lane >> 2);
        #pragma unroll
        for (int ni = 0; ni < 2; ni++) {
            int cl = n0w + 8 * ni + 2 * (lane & 3);
            float bb0 = __ldg(b2 + cl), bb1 = __ldg(b2 + cl + 1);
            float* d0 = q + (size_t)r * NQ + cl;
            *(float2*)d0 = make_float2(acc[mi][ni][0] + bb0, acc[mi][ni][1] + bb1);
            *(float2*)(d0 + 8 * NQ) = make_float2(acc[mi][ni][2] + bb0, acc[mi][ni][3] + bb1);
        }
    }
}

// ---------------------------------------------------------------------------
extern "C" void kernel_launch(void* const* d_in, const int* in_sizes, int n_in,
                              void* d_out, int out_size)
{
    const float* obs = (const float*)d_in[0];
    const float* act = (const float*)d_in[1];
    const float* hst = (const float*)d_in[2];
    const float* cst = (const float*)d_in[3];
    const float* W1  = (const float*)d_in[4];
    const float* b1  = (const float*)d_in[5];
    const float* Wih = (const float*)d_in[6];
    const float* bih = (const float*)d_in[7];
    const float* Whh = (const float*)d_in[8];
    const float* bhh = (const float*)d_in[9];
    const float* W2  = (const float*)d_in[10];
    const float* b2  = (const float*)d_in[11];
    float* out = (float*)d_out;

    cudaFuncSetAttribute(gemm1_kernel,
                         cudaFuncAttributeMaxDynamicSharedMemorySize, GSMEM1);
    cudaFuncSetAttribute(gemm2_kernel,
                         cudaFuncAttributeMaxDynamicSharedMemorySize, GSMEM2);
    cudaFuncSetAttribute(q_mma_kernel,
                         cudaFuncAttributeMaxDynamicSharedMemorySize, QSMEM);

    // W1/W2 conversion + hvec in one launch; W_ih converts inside gemm1's tail.
    prep_kernel<<<NCONV + 256, 256>>>(W1, W2, Whh, hst, bih, bhh);

    gemm1_kernel<<<dim3(EMB / 256, B_ROWS / 128), 256, GSMEM1>>>(obs, act, b1, Wih);
    gemm2_kernel<<<dim3(HID / 64, B_ROWS / 128), 256, GSMEM2>>>(cst, out);
    q_mma_kernel<<<B_ROWS / 128, 128, QSMEM>>>(b2, out);
}